// round 1
// baseline (speedup 1.0000x reference)
#include <cuda_runtime.h>
#include <cuda_bf16.h>

// ---------------- problem constants ----------------
#define LE 2048
#define LA 2048
#define CM 256          // d_model
#define HN 8            // heads
#define DH 32           // head dim
#define DF 1024         // ffn dim
#define LQ 3072         // 2048 + 1024 remain
#define LK 4096         // 2048 + 2048
#define SCALE 0.17677669529663687f   // 1/sqrt(32)

// ---------------- scratch (device globals; no allocation) ----------------
__device__ float d_fusedin[LE * 2 * CM];
__device__ float d_h1[LE * CM];
__device__ float d_h2[LE * CM];
__device__ float d_fused[LE * CM];
__device__ float d_q[LQ * CM];
__device__ float d_kv[LK * CM];
__device__ float d_Q[LQ * CM];
__device__ float d_K[LK * CM];
__device__ float d_V[LK * CM];
__device__ float d_attn[LQ * CM];
__device__ float d_res1[LQ * CM];
__device__ float d_yq[LQ * CM];
__device__ float d_ffh[LQ * DF];
__device__ float d_res2[LQ * CM];
__device__ int d_matched[LE];
__device__ int d_afe[LE];
__device__ int d_unmatched[LA];
__device__ int d_remain[LA];

// ---------------- matching ----------------
__global__ void match_ego_k(const int* __restrict__ pe, const int* __restrict__ pa) {
    int i = blockIdx.x * blockDim.x + threadIdx.x;
    if (i >= LE) return;
    int p = pe[i];
    int m = 0, a = 0;
    for (int j = 0; j < LA; j++) {
        if (pa[j] == p) { m = 1; a = j; break; }
    }
    d_matched[i] = m;
    d_afe[i] = a;
}

__global__ void match_agent_k(const int* __restrict__ pe, const int* __restrict__ pa) {
    int j = blockIdx.x * blockDim.x + threadIdx.x;
    if (j >= LA) return;
    int p = pa[j];
    int um = 1;
    for (int i = 0; i < LE; i++) {
        if (pe[i] == p) { um = 0; break; }
    }
    d_unmatched[j] = um;
}

__global__ void compact_k() {
    if (threadIdx.x == 0 && blockIdx.x == 0) {
        int c = 0;
        for (int j = 0; j < LA; j++)
            if (d_unmatched[j]) d_remain[c++] = j;
    }
}

// ---------------- gather/assembly ----------------
__global__ void build_fusedin_k(const float* __restrict__ xe, const float* __restrict__ xa) {
    int idx = blockIdx.x * blockDim.x + threadIdx.x;   // over LE * 2C
    if (idx >= LE * 2 * CM) return;
    int row = idx >> 9;            // /512
    int c = idx & 511;
    float v;
    if (c < CM) v = xe[row * CM + c];
    else v = xa[d_afe[row] * CM + (c - CM)];
    d_fusedin[idx] = v;
}

__global__ void build_q_k(const float* __restrict__ xe, const float* __restrict__ xa) {
    int idx = blockIdx.x * blockDim.x + threadIdx.x;   // over LQ * C
    if (idx >= LQ * CM) return;
    int row = idx >> 8;
    int c = idx & 255;
    float v;
    if (row < LE) v = d_matched[row] ? d_fused[row * CM + c] : xe[row * CM + c];
    else v = xa[d_remain[row - LE] * CM + c];
    d_q[idx] = v;
}

__global__ void build_kv_k(const float* __restrict__ xe, const float* __restrict__ xa) {
    int idx = blockIdx.x * blockDim.x + threadIdx.x;   // over LK * C
    if (idx >= LK * CM) return;
    int row = idx >> 8;
    int c = idx & 255;
    d_kv[idx] = (row < LE) ? xe[row * CM + c] : xa[(row - LE) * CM + c];
}

// ---------------- SGEMM: C[M,N] = act(A[M,K] @ W[N,K]^T + bias (+ R)) ----------------
// BM=BN=64, BK=16, 256 threads, 4x4 per thread.
template <bool RELU, bool RESID>
__global__ void gemm_k(const float* __restrict__ A, const float* __restrict__ W,
                       const float* __restrict__ bias, const float* __restrict__ Rm,
                       float* __restrict__ Cm, int M, int N, int K) {
    __shared__ float As[16][64];
    __shared__ float Ws[16][64];
    int tid = threadIdx.x;
    int tx = tid & 15, ty = tid >> 4;
    int bm = blockIdx.y << 6, bn = blockIdx.x << 6;
    int lr = tid >> 2;               // 0..63
    int lk = (tid & 3) << 2;         // 0,4,8,12
    const float* Ap = A + (bm + lr) * K + lk;
    const float* Wp = W + (bn + lr) * K + lk;

    float acc[4][4];
#pragma unroll
    for (int i = 0; i < 4; i++)
#pragma unroll
        for (int j = 0; j < 4; j++) acc[i][j] = 0.f;

    for (int k0 = 0; k0 < K; k0 += 16) {
        float4 a4 = *(const float4*)(Ap + k0);
        float4 w4 = *(const float4*)(Wp + k0);
        As[lk + 0][lr] = a4.x; As[lk + 1][lr] = a4.y;
        As[lk + 2][lr] = a4.z; As[lk + 3][lr] = a4.w;
        Ws[lk + 0][lr] = w4.x; Ws[lk + 1][lr] = w4.y;
        Ws[lk + 2][lr] = w4.z; Ws[lk + 3][lr] = w4.w;
        __syncthreads();
#pragma unroll
        for (int k = 0; k < 16; k++) {
            float4 av = *(const float4*)&As[k][ty << 2];
            float4 wv = *(const float4*)&Ws[k][tx << 2];
            float am[4] = {av.x, av.y, av.z, av.w};
            float wn[4] = {wv.x, wv.y, wv.z, wv.w};
#pragma unroll
            for (int i = 0; i < 4; i++)
#pragma unroll
                for (int j = 0; j < 4; j++)
                    acc[i][j] += am[i] * wn[j];
        }
        __syncthreads();
    }

#pragma unroll
    for (int i = 0; i < 4; i++) {
        int m = bm + (ty << 2) + i;
#pragma unroll
        for (int j = 0; j < 4; j++) {
            int n = bn + (tx << 2) + j;
            float v = acc[i][j] + bias[n];
            if (RESID) v += Rm[m * N + n];
            if (RELU) v = fmaxf(v, 0.f);
            Cm[m * N + n] = v;
        }
    }
}

// ---------------- flash attention: per-(head, 64-query-tile) block ----------------
__global__ void attn_k(const float* __restrict__ Q, const float* __restrict__ K,
                       const float* __restrict__ V, float* __restrict__ O) {
    __shared__ float Qs[64][32];
    __shared__ float Ks[64][36];   // pad 36: conflict-free float4 reads for j = 4*jj+qd
    __shared__ float Vs[64][36];
    __shared__ float Ss[64][65];   // pad 65: conflict-free scalar broadcast reads

    int h = blockIdx.y;
    int q0 = blockIdx.x << 6;
    int tid = threadIdx.x;

    for (int e = tid; e < 64 * 8; e += 256) {
        int r = e >> 3, c4 = (e & 7) << 2;
        *(float4*)&Qs[r][c4] = *(const float4*)(Q + (q0 + r) * CM + h * DH + c4);
    }
    __syncthreads();

    int r = tid >> 2;      // query row within tile (0..63)
    int qd = tid & 3;      // quad lane
    int c0 = qd << 3;      // 8 output columns owned

    float qreg[32];
#pragma unroll
    for (int d = 0; d < 32; d++) qreg[d] = Qs[r][d];

    float m_i = -1e30f, l_i = 0.f;
    float acc[8];
#pragma unroll
    for (int c = 0; c < 8; c++) acc[c] = 0.f;

    for (int kc = 0; kc < LK; kc += 64) {
        __syncthreads();  // previous iter's Ks/Vs readers done
        for (int e = tid; e < 64 * 8; e += 256) {
            int rr = e >> 3, c4 = (e & 7) << 2;
            *(float4*)&Ks[rr][c4] = *(const float4*)(K + (kc + rr) * CM + h * DH + c4);
            *(float4*)&Vs[rr][c4] = *(const float4*)(V + (kc + rr) * CM + h * DH + c4);
        }
        __syncthreads();

        float sv[16];
        float smax = -1e30f;
#pragma unroll
        for (int jj = 0; jj < 16; jj++) {
            int j = (jj << 2) + qd;
            float s = 0.f;
#pragma unroll
            for (int dd = 0; dd < 8; dd++) {
                float4 k4 = *(const float4*)&Ks[j][dd << 2];
                s += qreg[dd * 4 + 0] * k4.x + qreg[dd * 4 + 1] * k4.y +
                     qreg[dd * 4 + 2] * k4.z + qreg[dd * 4 + 3] * k4.w;
            }
            s *= SCALE;
            sv[jj] = s;
            smax = fmaxf(smax, s);
        }
        smax = fmaxf(smax, __shfl_xor_sync(0xffffffffu, smax, 1));
        smax = fmaxf(smax, __shfl_xor_sync(0xffffffffu, smax, 2));

        float m_new = fmaxf(m_i, smax);
        float corr = __expf(m_i - m_new);
        float lsum = 0.f;
#pragma unroll
        for (int jj = 0; jj < 16; jj++) {
            float p = __expf(sv[jj] - m_new);
            Ss[r][(jj << 2) + qd] = p;
            lsum += p;
        }
        lsum += __shfl_xor_sync(0xffffffffu, lsum, 1);
        lsum += __shfl_xor_sync(0xffffffffu, lsum, 2);
        l_i = l_i * corr + lsum;
        m_i = m_new;
#pragma unroll
        for (int c = 0; c < 8; c++) acc[c] *= corr;
        __syncwarp();  // Ss row written by own quad only (same warp)

#pragma unroll 4
        for (int j = 0; j < 64; j++) {
            float p = Ss[r][j];
            float4 v0 = *(const float4*)&Vs[j][c0];
            float4 v1 = *(const float4*)&Vs[j][c0 + 4];
            acc[0] += p * v0.x; acc[1] += p * v0.y;
            acc[2] += p * v0.z; acc[3] += p * v0.w;
            acc[4] += p * v1.x; acc[5] += p * v1.y;
            acc[6] += p * v1.z; acc[7] += p * v1.w;
        }
    }

    float inv = 1.f / l_i;
#pragma unroll
    for (int c = 0; c < 8; c++)
        O[(q0 + r) * CM + h * DH + c0 + c] = acc[c] * inv;
}

// ---------------- LayerNorm: one 256-thread block per row ----------------
__global__ void ln_k(const float* __restrict__ X, const float* __restrict__ g,
                     const float* __restrict__ b, float* __restrict__ Y) {
    int row = blockIdx.x;
    int c = threadIdx.x;
    float v = X[row * CM + c];
    float s = v, s2 = v * v;
#pragma unroll
    for (int o = 16; o > 0; o >>= 1) {
        s += __shfl_xor_sync(0xffffffffu, s, o);
        s2 += __shfl_xor_sync(0xffffffffu, s2, o);
    }
    __shared__ float rs[8], rs2[8];
    int w = c >> 5, lane = c & 31;
    if (lane == 0) { rs[w] = s; rs2[w] = s2; }
    __syncthreads();
    float tot = 0.f, tot2 = 0.f;
#pragma unroll
    for (int i = 0; i < 8; i++) { tot += rs[i]; tot2 += rs2[i]; }
    float mean = tot * (1.f / 256.f);
    float var = tot2 * (1.f / 256.f) - mean * mean;
    float is = rsqrtf(var + 1e-5f);
    Y[row * CM + c] = (v - mean) * is * g[c] + b[c];
}

// ---------------- launcher ----------------
extern "C" void kernel_launch(void* const* d_in, const int* in_sizes, int n_in,
                              void* d_out, int out_size) {
    const float* x_ego  = (const float*)d_in[0];
    const float* x_agent = (const float*)d_in[1];
    const float* Wf1 = (const float*)d_in[2];
    const float* bf1 = (const float*)d_in[3];
    const float* Wf2 = (const float*)d_in[4];
    const float* bf2 = (const float*)d_in[5];
    const float* Wf3 = (const float*)d_in[6];
    const float* bf3 = (const float*)d_in[7];
    const float* Wqkv = (const float*)d_in[8];
    const float* bqkv = (const float*)d_in[9];
    const float* Wo = (const float*)d_in[10];
    const float* bo = (const float*)d_in[11];
    const float* W1 = (const float*)d_in[12];
    const float* b1 = (const float*)d_in[13];
    const float* W2 = (const float*)d_in[14];
    const float* b2 = (const float*)d_in[15];
    const float* g1 = (const float*)d_in[16];
    const float* be1 = (const float*)d_in[17];
    const float* g2 = (const float*)d_in[18];
    const float* be2 = (const float*)d_in[19];
    const int* pos_ego = (const int*)d_in[20];
    const int* pos_agent = (const int*)d_in[21];
    float* out = (float*)d_out;

    float *p_fusedin, *p_h1, *p_h2, *p_fused, *p_q, *p_kv, *p_Q, *p_K, *p_V;
    float *p_attn, *p_res1, *p_yq, *p_ffh, *p_res2;
    cudaGetSymbolAddress((void**)&p_fusedin, d_fusedin);
    cudaGetSymbolAddress((void**)&p_h1, d_h1);
    cudaGetSymbolAddress((void**)&p_h2, d_h2);
    cudaGetSymbolAddress((void**)&p_fused, d_fused);
    cudaGetSymbolAddress((void**)&p_q, d_q);
    cudaGetSymbolAddress((void**)&p_kv, d_kv);
    cudaGetSymbolAddress((void**)&p_Q, d_Q);
    cudaGetSymbolAddress((void**)&p_K, d_K);
    cudaGetSymbolAddress((void**)&p_V, d_V);
    cudaGetSymbolAddress((void**)&p_attn, d_attn);
    cudaGetSymbolAddress((void**)&p_res1, d_res1);
    cudaGetSymbolAddress((void**)&p_yq, d_yq);
    cudaGetSymbolAddress((void**)&p_ffh, d_ffh);
    cudaGetSymbolAddress((void**)&p_res2, d_res2);

    // 1) position matching
    match_ego_k<<<LE / 256, 256>>>(pos_ego, pos_agent);
    match_agent_k<<<LA / 256, 256>>>(pos_ego, pos_agent);
    compact_k<<<1, 32>>>();

    // 2) query-fusion MLP
    build_fusedin_k<<<(LE * 2 * CM) / 256, 256>>>(x_ego, x_agent);
    gemm_k<true, false><<<dim3(CM / 64, LE / 64), 256>>>(p_fusedin, Wf1, bf1, nullptr, p_h1, LE, CM, 2 * CM);
    gemm_k<true, false><<<dim3(CM / 64, LE / 64), 256>>>(p_h1, Wf2, bf2, nullptr, p_h2, LE, CM, CM);
    gemm_k<false, false><<<dim3(CM / 64, LE / 64), 256>>>(p_h2, Wf3, bf3, nullptr, p_fused, LE, CM, CM);

    // 3) assemble q and kv sequences
    build_q_k<<<(LQ * CM) / 256, 256>>>(x_ego, x_agent);
    build_kv_k<<<(LK * CM) / 256, 256>>>(x_ego, x_agent);

    // 4) QKV projections (Wqkv rows: [0:256]=Q, [256:512]=K, [512:768]=V)
    gemm_k<false, false><<<dim3(CM / 64, LQ / 64), 256>>>(p_q, Wqkv, bqkv, nullptr, p_Q, LQ, CM, CM);
    gemm_k<false, false><<<dim3(CM / 64, LK / 64), 256>>>(p_kv, Wqkv + CM * CM, bqkv + CM, nullptr, p_K, LK, CM, CM);
    gemm_k<false, false><<<dim3(CM / 64, LK / 64), 256>>>(p_kv, Wqkv + 2 * CM * CM, bqkv + 2 * CM, nullptr, p_V, LK, CM, CM);

    // 5) attention
    attn_k<<<dim3(LQ / 64, HN), 256>>>(p_Q, p_K, p_V, p_attn);

    // 6) out-proj + residual, LN1
    gemm_k<false, true><<<dim3(CM / 64, LQ / 64), 256>>>(p_attn, Wo, bo, p_q, p_res1, LQ, CM, CM);
    ln_k<<<LQ, 256>>>(p_res1, g1, be1, p_yq);

    // 7) FFN + residual, LN2 -> out
    gemm_k<true, false><<<dim3(DF / 64, LQ / 64), 256>>>(p_yq, W1, b1, nullptr, p_ffh, LQ, DF, CM);
    gemm_k<false, true><<<dim3(CM / 64, LQ / 64), 256>>>(p_ffh, W2, b2, p_yq, p_res2, LQ, CM, DF);
    ln_k<<<LQ, 256>>>(p_res2, g2, be2, out);
}

// round 4
// speedup vs baseline: 2.5223x; 2.5223x over previous
#include <cuda_runtime.h>
#include <cuda_bf16.h>
#include <cstdint>

// ---------------- problem constants ----------------
#define LE 2048
#define LA 2048
#define CM 256          // d_model
#define HN 8            // heads
#define DH 32           // head dim
#define DF 1024         // ffn dim
#define LQ 3072         // 2048 + 1024 remain
#define LK 4096         // 2048 + 2048
#define SCALE 0.17677669529663687f   // 1/sqrt(32)

// ---------------- fp32 scratch ----------------
__device__ float d_fusedin[LE * 2 * CM];
__device__ float d_h1[LE * CM];
__device__ float d_h2[LE * CM];
__device__ float d_fused[LE * CM];
__device__ float d_q[LQ * CM];
__device__ float d_kv[LK * CM];
__device__ float d_Q[LQ * CM];
__device__ float d_K[LK * CM];
__device__ float d_V[LK * CM];
__device__ float d_attn[LQ * CM];
__device__ float d_res1[LQ * CM];
__device__ float d_yq[LQ * CM];
__device__ float d_ffh[LQ * DF];
__device__ float d_res2[LQ * CM];
__device__ int d_matched[LE];
__device__ int d_afe[LE];
__device__ int d_unmatched[LA];
__device__ int d_remain[LA];

// ---------------- bf16 scratch (hi/lo splits + attention operands) ----------------
__device__ __nv_bfloat16 b_fi_h[LE * 2 * CM], b_fi_l[LE * 2 * CM];
__device__ __nv_bfloat16 b_h1_h[LE * CM], b_h1_l[LE * CM];
__device__ __nv_bfloat16 b_h2_h[LE * CM], b_h2_l[LE * CM];
__device__ __nv_bfloat16 b_q_h[LQ * CM], b_q_l[LQ * CM];
__device__ __nv_bfloat16 b_kv_h[LK * CM], b_kv_l[LK * CM];
__device__ __nv_bfloat16 b_Q[LQ * CM];
__device__ __nv_bfloat16 b_K[LK * CM];
__device__ __nv_bfloat16 b_V[LK * CM];
__device__ __nv_bfloat16 b_at_h[LQ * CM], b_at_l[LQ * CM];
__device__ __nv_bfloat16 b_yq_h[LQ * CM], b_yq_l[LQ * CM];
__device__ __nv_bfloat16 b_ff_h[LQ * DF], b_ff_l[LQ * DF];
__device__ __nv_bfloat16 b_wf1_h[CM * 2 * CM], b_wf1_l[CM * 2 * CM];
__device__ __nv_bfloat16 b_wf2_h[CM * CM], b_wf2_l[CM * CM];
__device__ __nv_bfloat16 b_wf3_h[CM * CM], b_wf3_l[CM * CM];
__device__ __nv_bfloat16 b_wqkv_h[3 * CM * CM], b_wqkv_l[3 * CM * CM];
__device__ __nv_bfloat16 b_wo_h[CM * CM], b_wo_l[CM * CM];
__device__ __nv_bfloat16 b_w1_h[DF * CM], b_w1_l[DF * CM];
__device__ __nv_bfloat16 b_w2_h[CM * DF], b_w2_l[CM * DF];

// ---------------- mma / ldmatrix helpers ----------------
static __device__ __forceinline__ uint32_t smem_u32(const void* p) {
    return (uint32_t)__cvta_generic_to_shared(p);
}
static __device__ __forceinline__ void ldm4(uint32_t* r, const void* p) {
    uint32_t a = smem_u32(p);
    asm volatile("ldmatrix.sync.aligned.m8n8.x4.shared.b16 {%0,%1,%2,%3}, [%4];\n"
                 : "=r"(r[0]), "=r"(r[1]), "=r"(r[2]), "=r"(r[3]) : "r"(a));
}
static __device__ __forceinline__ void ldm4t(uint32_t* r, const void* p) {
    uint32_t a = smem_u32(p);
    asm volatile("ldmatrix.sync.aligned.m8n8.x4.trans.shared.b16 {%0,%1,%2,%3}, [%4];\n"
                 : "=r"(r[0]), "=r"(r[1]), "=r"(r[2]), "=r"(r[3]) : "r"(a));
}
static __device__ __forceinline__ void mma_bf16(float* c, const uint32_t* a, const uint32_t* b) {
    asm volatile("mma.sync.aligned.m16n8k16.row.col.f32.bf16.bf16.f32 "
                 "{%0,%1,%2,%3}, {%4,%5,%6,%7}, {%8,%9}, {%0,%1,%2,%3};\n"
                 : "+f"(c[0]), "+f"(c[1]), "+f"(c[2]), "+f"(c[3])
                 : "r"(a[0]), "r"(a[1]), "r"(a[2]), "r"(a[3]), "r"(b[0]), "r"(b[1]));
}
static __device__ __forceinline__ uint32_t packbf(float lo, float hi) {
    uint32_t r;
    asm("cvt.rn.bf16x2.f32 %0, %1, %2;" : "=r"(r) : "f"(hi), "f"(lo));
    return r;
}

// ---------------- matching ----------------
__global__ void match_ego_k(const int* __restrict__ pe, const int* __restrict__ pa) {
    int i = blockIdx.x * blockDim.x + threadIdx.x;
    if (i >= LE) return;
    int p = pe[i];
    int m = 0, a = 0;
    for (int j = 0; j < LA; j++)
        if (pa[j] == p) { m = 1; a = j; break; }
    d_matched[i] = m;
    d_afe[i] = a;
}
__global__ void match_agent_k(const int* __restrict__ pe, const int* __restrict__ pa) {
    int j = blockIdx.x * blockDim.x + threadIdx.x;
    if (j >= LA) return;
    int p = pa[j];
    int um = 1;
    for (int i = 0; i < LE; i++)
        if (pe[i] == p) { um = 0; break; }
    d_unmatched[j] = um;
}
__global__ void compact_k() {
    if (threadIdx.x == 0 && blockIdx.x == 0) {
        int c = 0;
        for (int j = 0; j < LA; j++)
            if (d_unmatched[j]) d_remain[c++] = j;
    }
}

// ---------------- gather/assembly ----------------
__global__ void build_fusedin_k(const float* __restrict__ xe, const float* __restrict__ xa) {
    int idx = blockIdx.x * blockDim.x + threadIdx.x;
    if (idx >= LE * 2 * CM) return;
    int row = idx >> 9;
    int c = idx & 511;
    float v;
    if (c < CM) v = xe[row * CM + c];
    else v = xa[d_afe[row] * CM + (c - CM)];
    d_fusedin[idx] = v;
}
__global__ void build_q_k(const float* __restrict__ xe, const float* __restrict__ xa) {
    int idx = blockIdx.x * blockDim.x + threadIdx.x;
    if (idx >= LQ * CM) return;
    int row = idx >> 8;
    int c = idx & 255;
    float v;
    if (row < LE) v = d_matched[row] ? d_fused[row * CM + c] : xe[row * CM + c];
    else v = xa[d_remain[row - LE] * CM + c];
    d_q[idx] = v;
}
__global__ void build_kv_k(const float* __restrict__ xe, const float* __restrict__ xa) {
    int idx = blockIdx.x * blockDim.x + threadIdx.x;
    if (idx >= LK * CM) return;
    int row = idx >> 8;
    int c = idx & 255;
    d_kv[idx] = (row < LE) ? xe[row * CM + c] : xa[(row - LE) * CM + c];
}

// ---------------- conversions ----------------
__global__ void cvt_split_k(const float* __restrict__ x, __nv_bfloat16* __restrict__ h,
                            __nv_bfloat16* __restrict__ l, int n) {
    int i = blockIdx.x * blockDim.x + threadIdx.x;
    if (i >= n) return;
    float v = x[i];
    __nv_bfloat16 hh = __float2bfloat16_rn(v);
    h[i] = hh;
    l[i] = __float2bfloat16_rn(v - __bfloat162float(hh));
}
__global__ void cvt_k(const float* __restrict__ x, __nv_bfloat16* __restrict__ h, int n) {
    int i = blockIdx.x * blockDim.x + threadIdx.x;
    if (i >= n) return;
    h[i] = __float2bfloat16_rn(x[i]);
}

// ---------------- split-bf16 tensor-core GEMM ----------------
// C[M,N] = act(A@W^T + bias (+R)), A = Ah+Al, W = Wh+Wl (3 mma passes: hh, hl, lh).
// BM=128, BN=64, BK=32, 256 threads, warp grid 4x2 (each warp 32x32 output).
template <bool RELU, bool RESID>
__global__ void gemm_bs_k(const __nv_bfloat16* __restrict__ Ah, const __nv_bfloat16* __restrict__ Al,
                          const __nv_bfloat16* __restrict__ Wh, const __nv_bfloat16* __restrict__ Wl,
                          const float* __restrict__ bias, const float* __restrict__ Rm,
                          float* __restrict__ Cm, int M, int N, int K) {
    __shared__ __nv_bfloat16 As[2][128][40];
    __shared__ __nv_bfloat16 Ws[2][64][40];
    int tid = threadIdx.x, lane = tid & 31, wid = tid >> 5;
    int bm = blockIdx.y << 7, bn = blockIdx.x << 6;
    int wm = (wid >> 1) << 5, wn = (wid & 1) << 5;

    float acc[2][4][4];
#pragma unroll
    for (int i = 0; i < 2; i++)
#pragma unroll
        for (int j = 0; j < 4; j++)
#pragma unroll
            for (int k = 0; k < 4; k++) acc[i][j][k] = 0.f;

    int ar = tid >> 1, ac = (tid & 1) << 4;     // A tile: 128 rows x 32, 2 chunks of 16
    int wr = tid >> 2, wc = (tid & 3) << 3;     // W tile: 64 rows x 32, 4 chunks of 8
    const __nv_bfloat16* gAh = Ah + (size_t)(bm + ar) * K + ac;
    const __nv_bfloat16* gAl = Al + (size_t)(bm + ar) * K + ac;
    const __nv_bfloat16* gWh = Wh + (size_t)(bn + wr) * K + wc;
    const __nv_bfloat16* gWl = Wl + (size_t)(bn + wr) * K + wc;

    int a_r = lane & 15, a_c = (lane >> 4) << 3;                      // A-frag ldmatrix addr
    int b_r = (lane & 7) + ((lane >> 4) << 3), b_c = ((lane >> 3) & 1) << 3;  // B-frag addr

    for (int k0 = 0; k0 < K; k0 += 32) {
        const uint4* p;
        p = (const uint4*)(gAh + k0);
        *(uint4*)&As[0][ar][ac] = p[0];
        *(uint4*)&As[0][ar][ac + 8] = p[1];
        p = (const uint4*)(gAl + k0);
        *(uint4*)&As[1][ar][ac] = p[0];
        *(uint4*)&As[1][ar][ac + 8] = p[1];
        *(uint4*)&Ws[0][wr][wc] = *(const uint4*)(gWh + k0);
        *(uint4*)&Ws[1][wr][wc] = *(const uint4*)(gWl + k0);
        __syncthreads();
#pragma unroll
        for (int ks = 0; ks < 2; ks++) {
            uint32_t ah[2][4], al[2][4], bh[4][2], bl[4][2];
#pragma unroll
            for (int mt = 0; mt < 2; mt++) {
                ldm4(ah[mt], &As[0][wm + (mt << 4) + a_r][(ks << 4) + a_c]);
                ldm4(al[mt], &As[1][wm + (mt << 4) + a_r][(ks << 4) + a_c]);
            }
#pragma unroll
            for (int np = 0; np < 2; np++) {
                uint32_t t4[4];
                ldm4(t4, &Ws[0][wn + (np << 4) + b_r][(ks << 4) + b_c]);
                bh[np * 2][0] = t4[0]; bh[np * 2][1] = t4[1];
                bh[np * 2 + 1][0] = t4[2]; bh[np * 2 + 1][1] = t4[3];
                ldm4(t4, &Ws[1][wn + (np << 4) + b_r][(ks << 4) + b_c]);
                bl[np * 2][0] = t4[0]; bl[np * 2][1] = t4[1];
                bl[np * 2 + 1][0] = t4[2]; bl[np * 2 + 1][1] = t4[3];
            }
#pragma unroll
            for (int mt = 0; mt < 2; mt++)
#pragma unroll
                for (int nt = 0; nt < 4; nt++) {
                    mma_bf16(acc[mt][nt], ah[mt], bh[nt]);
                    mma_bf16(acc[mt][nt], ah[mt], bl[nt]);
                    mma_bf16(acc[mt][nt], al[mt], bh[nt]);
                }
        }
        __syncthreads();
    }

    int g = lane >> 2, qd = lane & 3;
#pragma unroll
    for (int mt = 0; mt < 2; mt++) {
        int r0 = bm + wm + (mt << 4) + g;
#pragma unroll
        for (int nt = 0; nt < 4; nt++) {
            int col = bn + wn + (nt << 3) + (qd << 1);
            float b0 = bias[col], b1 = bias[col + 1];
            float v0 = acc[mt][nt][0] + b0, v1 = acc[mt][nt][1] + b1;
            float v2 = acc[mt][nt][2] + b0, v3 = acc[mt][nt][3] + b1;
            if (RESID) {
                v0 += Rm[(size_t)r0 * N + col];     v1 += Rm[(size_t)r0 * N + col + 1];
                v2 += Rm[(size_t)(r0 + 8) * N + col]; v3 += Rm[(size_t)(r0 + 8) * N + col + 1];
            }
            if (RELU) {
                v0 = fmaxf(v0, 0.f); v1 = fmaxf(v1, 0.f);
                v2 = fmaxf(v2, 0.f); v3 = fmaxf(v3, 0.f);
            }
            *(float2*)&Cm[(size_t)r0 * N + col] = make_float2(v0, v1);
            *(float2*)&Cm[(size_t)(r0 + 8) * N + col] = make_float2(v2, v3);
        }
    }
}

// ---------------- flash attention with bf16 mma ----------------
// 128 threads (4 warps), 64 queries per block (warp = 16 q rows), kv tiles of 64.
__global__ void attn_mma_k(const __nv_bfloat16* __restrict__ Qb, const __nv_bfloat16* __restrict__ Kb,
                           const __nv_bfloat16* __restrict__ Vb, float* __restrict__ O) {
    __shared__ __nv_bfloat16 Qs[64][40];
    __shared__ __nv_bfloat16 Ks[64][40];
    __shared__ __nv_bfloat16 Vs[64][40];
    int tid = threadIdx.x, lane = tid & 31, wid = tid >> 5;
    int h = blockIdx.y, q0 = blockIdx.x << 6;
    int hc = h << 5;

    {
        int r = tid >> 1, c = (tid & 1) << 4;
        const uint4* p = (const uint4*)(Qb + (size_t)(q0 + r) * CM + hc + c);
        *(uint4*)&Qs[r][c] = p[0];
        *(uint4*)&Qs[r][c + 8] = p[1];
    }
    __syncthreads();

    int a_r = lane & 15, a_c = (lane >> 4) << 3;
    uint32_t qf[2][4];
    ldm4(qf[0], &Qs[(wid << 4) + a_r][a_c]);
    ldm4(qf[1], &Qs[(wid << 4) + a_r][16 + a_c]);

    float o[4][4];
#pragma unroll
    for (int i = 0; i < 4; i++)
#pragma unroll
        for (int j = 0; j < 4; j++) o[i][j] = 0.f;
    float m0 = -1e30f, m1 = -1e30f, l0 = 0.f, l1 = 0.f;

    int b_r = (lane & 7) + ((lane >> 4) << 3), b_c = ((lane >> 3) & 1) << 3;
    int ldr = tid >> 1, ldc = (tid & 1) << 4;

    for (int kc = 0; kc < LK; kc += 64) {
        __syncthreads();
        {
            const uint4* pk = (const uint4*)(Kb + (size_t)(kc + ldr) * CM + hc + ldc);
            *(uint4*)&Ks[ldr][ldc] = pk[0];
            *(uint4*)&Ks[ldr][ldc + 8] = pk[1];
            const uint4* pv = (const uint4*)(Vb + (size_t)(kc + ldr) * CM + hc + ldc);
            *(uint4*)&Vs[ldr][ldc] = pv[0];
            *(uint4*)&Vs[ldr][ldc + 8] = pv[1];
        }
        __syncthreads();

        // ---- S = Q @ K^T  (16 x 64 per warp) ----
        float s[8][4];
#pragma unroll
        for (int j = 0; j < 8; j++)
#pragma unroll
            for (int c = 0; c < 4; c++) s[j][c] = 0.f;
#pragma unroll
        for (int ks = 0; ks < 2; ks++) {
#pragma unroll
            for (int jp = 0; jp < 4; jp++) {
                uint32_t t4[4];
                ldm4(t4, &Ks[(jp << 4) + b_r][(ks << 4) + b_c]);
                uint32_t bb0[2] = {t4[0], t4[1]};
                uint32_t bb1[2] = {t4[2], t4[3]};
                mma_bf16(s[jp * 2], qf[ks], bb0);
                mma_bf16(s[jp * 2 + 1], qf[ks], bb1);
            }
        }
#pragma unroll
        for (int j = 0; j < 8; j++) {
            s[j][0] *= SCALE; s[j][1] *= SCALE; s[j][2] *= SCALE; s[j][3] *= SCALE;
        }

        // ---- online softmax (thread owns rows g and g+8 within warp tile) ----
        float rmax0 = -1e30f, rmax1 = -1e30f;
#pragma unroll
        for (int j = 0; j < 8; j++) {
            rmax0 = fmaxf(rmax0, fmaxf(s[j][0], s[j][1]));
            rmax1 = fmaxf(rmax1, fmaxf(s[j][2], s[j][3]));
        }
        rmax0 = fmaxf(rmax0, __shfl_xor_sync(0xffffffffu, rmax0, 1));
        rmax0 = fmaxf(rmax0, __shfl_xor_sync(0xffffffffu, rmax0, 2));
        rmax1 = fmaxf(rmax1, __shfl_xor_sync(0xffffffffu, rmax1, 1));
        rmax1 = fmaxf(rmax1, __shfl_xor_sync(0xffffffffu, rmax1, 2));

        float mn0 = fmaxf(m0, rmax0), mn1 = fmaxf(m1, rmax1);
        float c0 = __expf(m0 - mn0), c1 = __expf(m1 - mn1);
        float sum0 = 0.f, sum1 = 0.f;
        uint32_t pa[4][4];
#pragma unroll
        for (int jj = 0; jj < 4; jj++) {
            float p00 = __expf(s[2 * jj][0] - mn0),     p01 = __expf(s[2 * jj][1] - mn0);
            float p02 = __expf(s[2 * jj][2] - mn1),     p03 = __expf(s[2 * jj][3] - mn1);
            float p10 = __expf(s[2 * jj + 1][0] - mn0), p11 = __expf(s[2 * jj + 1][1] - mn0);
            float p12 = __expf(s[2 * jj + 1][2] - mn1), p13 = __expf(s[2 * jj + 1][3] - mn1);
            sum0 += p00 + p01 + p10 + p11;
            sum1 += p02 + p03 + p12 + p13;
            pa[jj][0] = packbf(p00, p01);
            pa[jj][1] = packbf(p02, p03);
            pa[jj][2] = packbf(p10, p11);
            pa[jj][3] = packbf(p12, p13);
        }
        sum0 += __shfl_xor_sync(0xffffffffu, sum0, 1);
        sum0 += __shfl_xor_sync(0xffffffffu, sum0, 2);
        sum1 += __shfl_xor_sync(0xffffffffu, sum1, 1);
        sum1 += __shfl_xor_sync(0xffffffffu, sum1, 2);
        l0 = l0 * c0 + sum0;
        l1 = l1 * c1 + sum1;
        m0 = mn0; m1 = mn1;
#pragma unroll
        for (int nt = 0; nt < 4; nt++) {
            o[nt][0] *= c0; o[nt][1] *= c0; o[nt][2] *= c1; o[nt][3] *= c1;
        }

        // ---- O += P @ V  (V via ldmatrix.trans) ----
#pragma unroll
        for (int jj = 0; jj < 4; jj++) {
            uint32_t t4[4];
            ldm4t(t4, &Vs[(jj << 4) + (lane & 15)][(lane >> 4) << 3]);
            {
                uint32_t bb0[2] = {t4[0], t4[1]};
                uint32_t bb1[2] = {t4[2], t4[3]};
                mma_bf16(o[0], pa[jj], bb0);
                mma_bf16(o[1], pa[jj], bb1);
            }
            ldm4t(t4, &Vs[(jj << 4) + (lane & 15)][16 + ((lane >> 4) << 3)]);
            {
                uint32_t bb0[2] = {t4[0], t4[1]};
                uint32_t bb1[2] = {t4[2], t4[3]};
                mma_bf16(o[2], pa[jj], bb0);
                mma_bf16(o[3], pa[jj], bb1);
            }
        }
    }

    float inv0 = 1.f / l0, inv1 = 1.f / l1;
    int g = lane >> 2, qd = lane & 3;
    int row0 = q0 + (wid << 4) + g;
#pragma unroll
    for (int nt = 0; nt < 4; nt++) {
        int col = hc + (nt << 3) + (qd << 1);
        *(float2*)&O[(size_t)row0 * CM + col] = make_float2(o[nt][0] * inv0, o[nt][1] * inv0);
        *(float2*)&O[(size_t)(row0 + 8) * CM + col] = make_float2(o[nt][2] * inv1, o[nt][3] * inv1);
    }
}

// ---------------- LayerNorm ----------------
__global__ void ln_k(const float* __restrict__ X, const float* __restrict__ g,
                     const float* __restrict__ b, float* __restrict__ Y) {
    int row = blockIdx.x;
    int c = threadIdx.x;
    float v = X[row * CM + c];
    float s = v, s2 = v * v;
#pragma unroll
    for (int o = 16; o > 0; o >>= 1) {
        s += __shfl_xor_sync(0xffffffffu, s, o);
        s2 += __shfl_xor_sync(0xffffffffu, s2, o);
    }
    __shared__ float rs[8], rs2[8];
    int w = c >> 5, lane = c & 31;
    if (lane == 0) { rs[w] = s; rs2[w] = s2; }
    __syncthreads();
    float tot = 0.f, tot2 = 0.f;
#pragma unroll
    for (int i = 0; i < 8; i++) { tot += rs[i]; tot2 += rs2[i]; }
    float mean = tot * (1.f / 256.f);
    float var = tot2 * (1.f / 256.f) - mean * mean;
    float is = rsqrtf(var + 1e-5f);
    Y[row * CM + c] = (v - mean) * is * g[c] + b[c];
}

// ---------------- launcher ----------------
#define SYM(p, s) cudaGetSymbolAddress((void**)&p, s)

extern "C" void kernel_launch(void* const* d_in, const int* in_sizes, int n_in,
                              void* d_out, int out_size) {
    const float* x_ego  = (const float*)d_in[0];
    const float* x_agent = (const float*)d_in[1];
    const float* Wf1 = (const float*)d_in[2];
    const float* bf1 = (const float*)d_in[3];
    const float* Wf2 = (const float*)d_in[4];
    const float* bf2 = (const float*)d_in[5];
    const float* Wf3 = (const float*)d_in[6];
    const float* bf3 = (const float*)d_in[7];
    const float* Wqkv = (const float*)d_in[8];
    const float* bqkv = (const float*)d_in[9];
    const float* Wo = (const float*)d_in[10];
    const float* bo = (const float*)d_in[11];
    const float* W1 = (const float*)d_in[12];
    const float* b1 = (const float*)d_in[13];
    const float* W2 = (const float*)d_in[14];
    const float* b2 = (const float*)d_in[15];
    const float* g1 = (const float*)d_in[16];
    const float* be1 = (const float*)d_in[17];
    const float* g2 = (const float*)d_in[18];
    const float* be2 = (const float*)d_in[19];
    const int* pos_ego = (const int*)d_in[20];
    const int* pos_agent = (const int*)d_in[21];
    float* out = (float*)d_out;

    float *p_fusedin, *p_h1, *p_h2, *p_fused, *p_q, *p_kv, *p_Q, *p_K, *p_V;
    float *p_attn, *p_res1, *p_yq, *p_ffh, *p_res2;
    SYM(p_fusedin, d_fusedin); SYM(p_h1, d_h1); SYM(p_h2, d_h2); SYM(p_fused, d_fused);
    SYM(p_q, d_q); SYM(p_kv, d_kv); SYM(p_Q, d_Q); SYM(p_K, d_K); SYM(p_V, d_V);
    SYM(p_attn, d_attn); SYM(p_res1, d_res1); SYM(p_yq, d_yq); SYM(p_ffh, d_ffh); SYM(p_res2, d_res2);

    __nv_bfloat16 *fi_h, *fi_l, *h1_h, *h1_l, *h2_h, *h2_l, *q_h, *q_l, *kv_h, *kv_l;
    __nv_bfloat16 *Qb, *Kb, *Vb, *at_h, *at_l, *yq_h, *yq_l, *ff_h, *ff_l;
    __nv_bfloat16 *wf1_h, *wf1_l, *wf2_h, *wf2_l, *wf3_h, *wf3_l;
    __nv_bfloat16 *wqkv_h, *wqkv_l, *wo_h, *wo_l, *w1_h, *w1_l, *w2_h, *w2_l;
    SYM(fi_h, b_fi_h); SYM(fi_l, b_fi_l);
    SYM(h1_h, b_h1_h); SYM(h1_l, b_h1_l);
    SYM(h2_h, b_h2_h); SYM(h2_l, b_h2_l);
    SYM(q_h, b_q_h); SYM(q_l, b_q_l);
    SYM(kv_h, b_kv_h); SYM(kv_l, b_kv_l);
    SYM(Qb, b_Q); SYM(Kb, b_K); SYM(Vb, b_V);
    SYM(at_h, b_at_h); SYM(at_l, b_at_l);
    SYM(yq_h, b_yq_h); SYM(yq_l, b_yq_l);
    SYM(ff_h, b_ff_h); SYM(ff_l, b_ff_l);
    SYM(wf1_h, b_wf1_h); SYM(wf1_l, b_wf1_l);
    SYM(wf2_h, b_wf2_h); SYM(wf2_l, b_wf2_l);
    SYM(wf3_h, b_wf3_h); SYM(wf3_l, b_wf3_l);
    SYM(wqkv_h, b_wqkv_h); SYM(wqkv_l, b_wqkv_l);
    SYM(wo_h, b_wo_h); SYM(wo_l, b_wo_l);
    SYM(w1_h, b_w1_h); SYM(w1_l, b_w1_l);
    SYM(w2_h, b_w2_h); SYM(w2_l, b_w2_l);

    // 1) matching
    match_ego_k<<<LE / 256, 256>>>(pos_ego, pos_agent);
    match_agent_k<<<LA / 256, 256>>>(pos_ego, pos_agent);
    compact_k<<<1, 32>>>();

    // weight hi/lo splits
    cvt_split_k<<<(CM * 2 * CM) / 256, 256>>>(Wf1, wf1_h, wf1_l, CM * 2 * CM);
    cvt_split_k<<<(CM * CM) / 256, 256>>>(Wf2, wf2_h, wf2_l, CM * CM);
    cvt_split_k<<<(CM * CM) / 256, 256>>>(Wf3, wf3_h, wf3_l, CM * CM);
    cvt_split_k<<<(3 * CM * CM) / 256, 256>>>(Wqkv, wqkv_h, wqkv_l, 3 * CM * CM);
    cvt_split_k<<<(CM * CM) / 256, 256>>>(Wo, wo_h, wo_l, CM * CM);
    cvt_split_k<<<(DF * CM) / 256, 256>>>(W1, w1_h, w1_l, DF * CM);
    cvt_split_k<<<(CM * DF) / 256, 256>>>(W2, w2_h, w2_l, CM * DF);

    // 2) fusion MLP (split precision)
    build_fusedin_k<<<(LE * 2 * CM) / 256, 256>>>(x_ego, x_agent);
    cvt_split_k<<<(LE * 2 * CM) / 256, 256>>>(p_fusedin, fi_h, fi_l, LE * 2 * CM);
    gemm_bs_k<true, false><<<dim3(CM / 64, LE / 128), 256>>>(fi_h, fi_l, wf1_h, wf1_l, bf1, nullptr, p_h1, LE, CM, 2 * CM);
    cvt_split_k<<<(LE * CM) / 256, 256>>>(p_h1, h1_h, h1_l, LE * CM);
    gemm_bs_k<true, false><<<dim3(CM / 64, LE / 128), 256>>>(h1_h, h1_l, wf2_h, wf2_l, bf2, nullptr, p_h2, LE, CM, CM);
    cvt_split_k<<<(LE * CM) / 256, 256>>>(p_h2, h2_h, h2_l, LE * CM);
    gemm_bs_k<false, false><<<dim3(CM / 64, LE / 128), 256>>>(h2_h, h2_l, wf3_h, wf3_l, bf3, nullptr, p_fused, LE, CM, CM);

    // 3) assemble sequences
    build_q_k<<<(LQ * CM) / 256, 256>>>(x_ego, x_agent);
    build_kv_k<<<(LK * CM) / 256, 256>>>(x_ego, x_agent);
    cvt_split_k<<<(LQ * CM) / 256, 256>>>(p_q, q_h, q_l, LQ * CM);
    cvt_split_k<<<(LK * CM) / 256, 256>>>(p_kv, kv_h, kv_l, LK * CM);

    // 4) QKV projections
    gemm_bs_k<false, false><<<dim3(CM / 64, LQ / 128), 256>>>(q_h, q_l, wqkv_h, wqkv_l, bqkv, nullptr, p_Q, LQ, CM, CM);
    cvt_k<<<(LQ * CM) / 256, 256>>>(p_Q, Qb, LQ * CM);
    gemm_bs_k<false, false><<<dim3(CM / 64, LK / 128), 256>>>(kv_h, kv_l, wqkv_h + CM * CM, wqkv_l + CM * CM, bqkv + CM, nullptr, p_K, LK, CM, CM);
    cvt_k<<<(LK * CM) / 256, 256>>>(p_K, Kb, LK * CM);
    gemm_bs_k<false, false><<<dim3(CM / 64, LK / 128), 256>>>(kv_h, kv_l, wqkv_h + 2 * CM * CM, wqkv_l + 2 * CM * CM, bqkv + 2 * CM, nullptr, p_V, LK, CM, CM);
    cvt_k<<<(LK * CM) / 256, 256>>>(p_V, Vb, LK * CM);

    // 5) attention
    attn_mma_k<<<dim3(LQ / 64, HN), 128>>>(Qb, Kb, Vb, p_attn);
    cvt_split_k<<<(LQ * CM) / 256, 256>>>(p_attn, at_h, at_l, LQ * CM);

    // 6) out-proj + residual, LN1
    gemm_bs_k<false, true><<<dim3(CM / 64, LQ / 128), 256>>>(at_h, at_l, wo_h, wo_l, bo, p_q, p_res1, LQ, CM, CM);
    ln_k<<<LQ, 256>>>(p_res1, g1, be1, p_yq);
    cvt_split_k<<<(LQ * CM) / 256, 256>>>(p_yq, yq_h, yq_l, LQ * CM);

    // 7) FFN + residual, LN2
    gemm_bs_k<true, false><<<dim3(DF / 64, LQ / 128), 256>>>(yq_h, yq_l, w1_h, w1_l, b1, nullptr, p_ffh, LQ, DF, CM);
    cvt_split_k<<<(LQ * DF) / 256, 256>>>(p_ffh, ff_h, ff_l, LQ * DF);
    gemm_bs_k<false, true><<<dim3(CM / 64, LQ / 128), 256>>>(ff_h, ff_l, w2_h, w2_l, b2, p_yq, p_res2, LQ, CM, DF);
    ln_k<<<LQ, 256>>>(p_res2, g2, be2, out);
}

// round 7
// speedup vs baseline: 4.3672x; 1.7314x over previous
#include <cuda_runtime.h>
#include <cuda_bf16.h>
#include <cstdint>

// ---------------- problem constants ----------------
#define LE 2048
#define LA 2048
#define CM 256          // d_model
#define HN 8            // heads
#define DH 32           // head dim
#define DF 1024         // ffn dim
#define LQ 3072         // 2048 + 1024 remain
#define LK 4096         // 2048 + 2048
#define SCALE 0.17677669529663687f   // 1/sqrt(32)

// ---------------- fp32 scratch ----------------
__device__ float d_fused[LE * CM];
__device__ float d_q[LQ * CM];
__device__ float d_res1[LQ * CM];
__device__ float d_yq[LQ * CM];
__device__ float d_res2[LQ * CM];
__device__ int d_matched[LE];
__device__ int d_afe[LE];
__device__ int d_unmatched[LA];
__device__ int d_remain[LA];

// ---------------- bf16 scratch ----------------
__device__ __nv_bfloat16 b_fi_h[LE * 2 * CM], b_fi_l[LE * 2 * CM];
__device__ __nv_bfloat16 b_h1_h[LE * CM], b_h1_l[LE * CM];
__device__ __nv_bfloat16 b_h2_h[LE * CM], b_h2_l[LE * CM];
__device__ __nv_bfloat16 b_q_h[LQ * CM], b_q_l[LQ * CM];
__device__ __nv_bfloat16 b_kv_h[LK * CM], b_kv_l[LK * CM];
__device__ __nv_bfloat16 b_Q[LQ * CM];
__device__ __nv_bfloat16 b_K[LK * CM];
__device__ __nv_bfloat16 b_V[LK * CM];
__device__ __nv_bfloat16 b_at_h[LQ * CM], b_at_l[LQ * CM];
__device__ __nv_bfloat16 b_yq_h[LQ * CM], b_yq_l[LQ * CM];
__device__ __nv_bfloat16 b_ff_h[LQ * DF], b_ff_l[LQ * DF];
__device__ __nv_bfloat16 b_wf1_h[CM * 2 * CM], b_wf1_l[CM * 2 * CM];
__device__ __nv_bfloat16 b_wf2_h[CM * CM], b_wf2_l[CM * CM];
__device__ __nv_bfloat16 b_wf3_h[CM * CM], b_wf3_l[CM * CM];
__device__ __nv_bfloat16 b_wqkv_h[3 * CM * CM], b_wqkv_l[3 * CM * CM];
__device__ __nv_bfloat16 b_wo_h[CM * CM], b_wo_l[CM * CM];
__device__ __nv_bfloat16 b_w1_h[DF * CM], b_w1_l[DF * CM];
__device__ __nv_bfloat16 b_w2_h[CM * DF], b_w2_l[CM * DF];

// ---------------- helpers ----------------
static __device__ __forceinline__ uint32_t smem_u32(const void* p) {
    return (uint32_t)__cvta_generic_to_shared(p);
}
static __device__ __forceinline__ void ldm4(uint32_t* r, const void* p) {
    uint32_t a = smem_u32(p);
    asm volatile("ldmatrix.sync.aligned.m8n8.x4.shared.b16 {%0,%1,%2,%3}, [%4];\n"
                 : "=r"(r[0]), "=r"(r[1]), "=r"(r[2]), "=r"(r[3]) : "r"(a));
}
static __device__ __forceinline__ void ldm4t(uint32_t* r, const void* p) {
    uint32_t a = smem_u32(p);
    asm volatile("ldmatrix.sync.aligned.m8n8.x4.trans.shared.b16 {%0,%1,%2,%3}, [%4];\n"
                 : "=r"(r[0]), "=r"(r[1]), "=r"(r[2]), "=r"(r[3]) : "r"(a));
}
static __device__ __forceinline__ void mma_bf16(float* c, const uint32_t* a, const uint32_t* b) {
    asm volatile("mma.sync.aligned.m16n8k16.row.col.f32.bf16.bf16.f32 "
                 "{%0,%1,%2,%3}, {%4,%5,%6,%7}, {%8,%9}, {%0,%1,%2,%3};\n"
                 : "+f"(c[0]), "+f"(c[1]), "+f"(c[2]), "+f"(c[3])
                 : "r"(a[0]), "r"(a[1]), "r"(a[2]), "r"(a[3]), "r"(b[0]), "r"(b[1]));
}
static __device__ __forceinline__ uint32_t packbf(float lo, float hi) {
    uint32_t r;
    asm("cvt.rn.bf16x2.f32 %0, %1, %2;" : "=r"(r) : "f"(hi), "f"(lo));
    return r;
}
// hi/lo split of two adjacent values, packed for 32-bit stores
static __device__ __forceinline__ void split2(float v0, float v1, uint32_t& ph, uint32_t& pl) {
    __nv_bfloat16 h0 = __float2bfloat16_rn(v0), h1 = __float2bfloat16_rn(v1);
    float l0 = v0 - __bfloat162float(h0);
    float l1 = v1 - __bfloat162float(h1);
    ph = ((uint32_t)__bfloat16_as_ushort(h1) << 16) | (uint32_t)__bfloat16_as_ushort(h0);
    pl = packbf(l0, l1);
}

// ---------------- matching (combined) ----------------
__global__ void match_k(const int* __restrict__ pe, const int* __restrict__ pa) {
    int i = blockIdx.x * blockDim.x + threadIdx.x;
    if (i < LE) {
        int p = pe[i];
        int m = 0, a = 0;
        for (int j = 0; j < LA; j++)
            if (pa[j] == p) { m = 1; a = j; break; }
        d_matched[i] = m;
        d_afe[i] = a;
    } else if (i < LE + LA) {
        int j = i - LE;
        int p = pa[j];
        int um = 1;
        for (int k = 0; k < LE; k++)
            if (pe[k] == p) { um = 0; break; }
        d_unmatched[j] = um;
    }
}

// ---------------- parallel compaction (single block, 1024 threads x 2 elems) ----------------
__global__ void compact_scan_k() {
    __shared__ int wsum[32];
    int t = threadIdx.x;
    int f0 = d_unmatched[2 * t], f1 = d_unmatched[2 * t + 1];
    int s = f0 + f1;
    int lane = t & 31, w = t >> 5;
    int v = s;
#pragma unroll
    for (int o = 1; o < 32; o <<= 1) {
        int n = __shfl_up_sync(0xffffffffu, v, o);
        if (lane >= o) v += n;
    }
    if (lane == 31) wsum[w] = v;
    __syncthreads();
    if (w == 0) {
        int x = wsum[lane];
#pragma unroll
        for (int o = 1; o < 32; o <<= 1) {
            int n = __shfl_up_sync(0xffffffffu, x, o);
            if (lane >= o) x += n;
        }
        wsum[lane] = x;
    }
    __syncthreads();
    int base = (w > 0 ? wsum[w - 1] : 0) + (v - s);
    if (f0) d_remain[base] = 2 * t;
    if (f1) d_remain[base + f0] = 2 * t + 1;
}

// ---------------- one-shot weight split ----------------
struct WS {
    const float* s[7];
    __nv_bfloat16* h[7];
    __nv_bfloat16* l[7];
    int off[8];
};
__global__ void wsplit_k(WS ws) {
    int i = blockIdx.x * blockDim.x + threadIdx.x;
    int r = 0;
#pragma unroll
    for (int j = 1; j < 7; j++)
        if (i >= ws.off[j]) r = j;
    int loc = i - ws.off[r];
    float v = ws.s[r][loc];
    __nv_bfloat16 hh = __float2bfloat16_rn(v);
    ws.h[r][loc] = hh;
    ws.l[r][loc] = __float2bfloat16_rn(v - __bfloat162float(hh));
}

// ---------------- fused builds (gather + split, no fp32 round-trip) ----------------
__global__ void build_fusedin_k(const float* __restrict__ xe, const float* __restrict__ xa) {
    int idx = blockIdx.x * blockDim.x + threadIdx.x;
    if (idx >= LE * 2 * CM) return;
    int row = idx >> 9;
    int c = idx & 511;
    float v = (c < CM) ? xe[row * CM + c] : xa[d_afe[row] * CM + (c - CM)];
    __nv_bfloat16 hh = __float2bfloat16_rn(v);
    b_fi_h[idx] = hh;
    b_fi_l[idx] = __float2bfloat16_rn(v - __bfloat162float(hh));
}
__global__ void build_q_k(const float* __restrict__ xe, const float* __restrict__ xa) {
    int idx = blockIdx.x * blockDim.x + threadIdx.x;
    if (idx >= LQ * CM) return;
    int row = idx >> 8;
    int c = idx & 255;
    float v;
    if (row < LE) v = d_matched[row] ? d_fused[idx] : xe[idx];
    else v = xa[d_remain[row - LE] * CM + c];
    d_q[idx] = v;
    __nv_bfloat16 hh = __float2bfloat16_rn(v);
    b_q_h[idx] = hh;
    b_q_l[idx] = __float2bfloat16_rn(v - __bfloat162float(hh));
}
__global__ void build_kv_k(const float* __restrict__ xe, const float* __restrict__ xa) {
    int idx = blockIdx.x * blockDim.x + threadIdx.x;
    if (idx >= LK * CM) return;
    int row = idx >> 8;
    float v = (row < LE) ? xe[idx] : xa[idx - LE * CM];
    __nv_bfloat16 hh = __float2bfloat16_rn(v);
    b_kv_h[idx] = hh;
    b_kv_l[idx] = __float2bfloat16_rn(v - __bfloat162float(hh));
}

// ---------------- split-bf16 tensor-core GEMM with fused output modes ----------------
// OMODE: 0 = fp32, 1 = hi/lo split, 2 = plain bf16, 3 = dual K/V bf16 (N=512)
#define OUT_F32 0
#define OUT_SPLIT 1
#define OUT_BF16 2
#define OUT_KV 3
template <int OMODE, bool RELU, bool RESID>
__global__ void gemm_bs_k(const __nv_bfloat16* __restrict__ Ah, const __nv_bfloat16* __restrict__ Al,
                          const __nv_bfloat16* __restrict__ Wh, const __nv_bfloat16* __restrict__ Wl,
                          const float* __restrict__ bias, const float* __restrict__ Rm,
                          float* __restrict__ Cf, __nv_bfloat16* __restrict__ Ch,
                          __nv_bfloat16* __restrict__ Cl, int M, int N, int K) {
    __shared__ __nv_bfloat16 As[2][128][40];
    __shared__ __nv_bfloat16 Ws[2][64][40];
    int tid = threadIdx.x, lane = tid & 31, wid = tid >> 5;
    int bm = blockIdx.y << 7, bn = blockIdx.x << 6;
    int wm = (wid >> 1) << 5, wn = (wid & 1) << 5;

    float acc[2][4][4];
#pragma unroll
    for (int i = 0; i < 2; i++)
#pragma unroll
        for (int j = 0; j < 4; j++)
#pragma unroll
            for (int k = 0; k < 4; k++) acc[i][j][k] = 0.f;

    int ar = tid >> 1, ac = (tid & 1) << 4;
    int wr = tid >> 2, wc = (tid & 3) << 3;
    const __nv_bfloat16* gAh = Ah + (size_t)(bm + ar) * K + ac;
    const __nv_bfloat16* gAl = Al + (size_t)(bm + ar) * K + ac;
    const __nv_bfloat16* gWh = Wh + (size_t)(bn + wr) * K + wc;
    const __nv_bfloat16* gWl = Wl + (size_t)(bn + wr) * K + wc;

    int a_r = lane & 15, a_c = (lane >> 4) << 3;
    int b_r = (lane & 7) + ((lane >> 4) << 3), b_c = ((lane >> 3) & 1) << 3;

    for (int k0 = 0; k0 < K; k0 += 32) {
        const uint4* p;
        p = (const uint4*)(gAh + k0);
        *(uint4*)&As[0][ar][ac] = p[0];
        *(uint4*)&As[0][ar][ac + 8] = p[1];
        p = (const uint4*)(gAl + k0);
        *(uint4*)&As[1][ar][ac] = p[0];
        *(uint4*)&As[1][ar][ac + 8] = p[1];
        *(uint4*)&Ws[0][wr][wc] = *(const uint4*)(gWh + k0);
        *(uint4*)&Ws[1][wr][wc] = *(const uint4*)(gWl + k0);
        __syncthreads();
#pragma unroll
        for (int ks = 0; ks < 2; ks++) {
            uint32_t ah[2][4], al[2][4], bh[4][2], bl[4][2];
#pragma unroll
            for (int mt = 0; mt < 2; mt++) {
                ldm4(ah[mt], &As[0][wm + (mt << 4) + a_r][(ks << 4) + a_c]);
                ldm4(al[mt], &As[1][wm + (mt << 4) + a_r][(ks << 4) + a_c]);
            }
#pragma unroll
            for (int np = 0; np < 2; np++) {
                uint32_t t4[4];
                ldm4(t4, &Ws[0][wn + (np << 4) + b_r][(ks << 4) + b_c]);
                bh[np * 2][0] = t4[0]; bh[np * 2][1] = t4[1];
                bh[np * 2 + 1][0] = t4[2]; bh[np * 2 + 1][1] = t4[3];
                ldm4(t4, &Ws[1][wn + (np << 4) + b_r][(ks << 4) + b_c]);
                bl[np * 2][0] = t4[0]; bl[np * 2][1] = t4[1];
                bl[np * 2 + 1][0] = t4[2]; bl[np * 2 + 1][1] = t4[3];
            }
#pragma unroll
            for (int mt = 0; mt < 2; mt++)
#pragma unroll
                for (int nt = 0; nt < 4; nt++) {
                    mma_bf16(acc[mt][nt], ah[mt], bh[nt]);
                    mma_bf16(acc[mt][nt], ah[mt], bl[nt]);
                    mma_bf16(acc[mt][nt], al[mt], bh[nt]);
                }
        }
        __syncthreads();
    }

    int g = lane >> 2, qd = lane & 3;
#pragma unroll
    for (int mt = 0; mt < 2; mt++) {
        int r0 = bm + wm + (mt << 4) + g;
#pragma unroll
        for (int nt = 0; nt < 4; nt++) {
            int col = bn + wn + (nt << 3) + (qd << 1);
            float b0 = bias[col], b1 = bias[col + 1];
            float v0 = acc[mt][nt][0] + b0, v1 = acc[mt][nt][1] + b1;
            float v2 = acc[mt][nt][2] + b0, v3 = acc[mt][nt][3] + b1;
            if (RESID) {
                v0 += Rm[(size_t)r0 * N + col];       v1 += Rm[(size_t)r0 * N + col + 1];
                v2 += Rm[(size_t)(r0 + 8) * N + col]; v3 += Rm[(size_t)(r0 + 8) * N + col + 1];
            }
            if (RELU) {
                v0 = fmaxf(v0, 0.f); v1 = fmaxf(v1, 0.f);
                v2 = fmaxf(v2, 0.f); v3 = fmaxf(v3, 0.f);
            }
            size_t i0 = (size_t)r0 * N + col, i1 = (size_t)(r0 + 8) * N + col;
            if (OMODE == OUT_F32) {
                *(float2*)&Cf[i0] = make_float2(v0, v1);
                *(float2*)&Cf[i1] = make_float2(v2, v3);
            } else if (OMODE == OUT_BF16) {
                *(uint32_t*)&Ch[i0] = packbf(v0, v1);
                *(uint32_t*)&Ch[i1] = packbf(v2, v3);
            } else if (OMODE == OUT_SPLIT) {
                uint32_t ph, pl;
                split2(v0, v1, ph, pl);
                *(uint32_t*)&Ch[i0] = ph; *(uint32_t*)&Cl[i0] = pl;
                split2(v2, v3, ph, pl);
                *(uint32_t*)&Ch[i1] = ph; *(uint32_t*)&Cl[i1] = pl;
            } else {  // OUT_KV: cols [0,256) -> Ch (K), [256,512) -> Cl (V), row stride CM
                __nv_bfloat16* dst = (col < CM) ? Ch : Cl;
                int cc = col & (CM - 1);
                *(uint32_t*)&dst[(size_t)r0 * CM + cc] = packbf(v0, v1);
                *(uint32_t*)&dst[(size_t)(r0 + 8) * CM + cc] = packbf(v2, v3);
            }
        }
    }
}

// ---------------- flash attention with bf16 mma, split-output epilogue ----------------
__global__ void attn_mma_k(const __nv_bfloat16* __restrict__ Qb, const __nv_bfloat16* __restrict__ Kb,
                           const __nv_bfloat16* __restrict__ Vb,
                           __nv_bfloat16* __restrict__ Oh, __nv_bfloat16* __restrict__ Ol) {
    __shared__ __nv_bfloat16 Qs[64][40];
    __shared__ __nv_bfloat16 Ks[64][40];
    __shared__ __nv_bfloat16 Vs[64][40];
    int tid = threadIdx.x, lane = tid & 31, wid = tid >> 5;
    int h = blockIdx.y, q0 = blockIdx.x << 6;
    int hc = h << 5;

    {
        int r = tid >> 1, c = (tid & 1) << 4;
        const uint4* p = (const uint4*)(Qb + (size_t)(q0 + r) * CM + hc + c);
        *(uint4*)&Qs[r][c] = p[0];
        *(uint4*)&Qs[r][c + 8] = p[1];
    }
    __syncthreads();

    int a_r = lane & 15, a_c = (lane >> 4) << 3;
    uint32_t qf[2][4];
    ldm4(qf[0], &Qs[(wid << 4) + a_r][a_c]);
    ldm4(qf[1], &Qs[(wid << 4) + a_r][16 + a_c]);

    float o[4][4];
#pragma unroll
    for (int i = 0; i < 4; i++)
#pragma unroll
        for (int j = 0; j < 4; j++) o[i][j] = 0.f;
    float m0 = -1e30f, m1 = -1e30f, l0 = 0.f, l1 = 0.f;

    int b_r = (lane & 7) + ((lane >> 4) << 3), b_c = ((lane >> 3) & 1) << 3;
    int ldr = tid >> 1, ldc = (tid & 1) << 4;

    for (int kc = 0; kc < LK; kc += 64) {
        __syncthreads();
        {
            const uint4* pk = (const uint4*)(Kb + (size_t)(kc + ldr) * CM + hc + ldc);
            *(uint4*)&Ks[ldr][ldc] = pk[0];
            *(uint4*)&Ks[ldr][ldc + 8] = pk[1];
            const uint4* pv = (const uint4*)(Vb + (size_t)(kc + ldr) * CM + hc + ldc);
            *(uint4*)&Vs[ldr][ldc] = pv[0];
            *(uint4*)&Vs[ldr][ldc + 8] = pv[1];
        }
        __syncthreads();

        float s[8][4];
#pragma unroll
        for (int j = 0; j < 8; j++)
#pragma unroll
            for (int c = 0; c < 4; c++) s[j][c] = 0.f;
#pragma unroll
        for (int ks = 0; ks < 2; ks++) {
#pragma unroll
            for (int jp = 0; jp < 4; jp++) {
                uint32_t t4[4];
                ldm4(t4, &Ks[(jp << 4) + b_r][(ks << 4) + b_c]);
                uint32_t bb0[2] = {t4[0], t4[1]};
                uint32_t bb1[2] = {t4[2], t4[3]};
                mma_bf16(s[jp * 2], qf[ks], bb0);
                mma_bf16(s[jp * 2 + 1], qf[ks], bb1);
            }
        }
#pragma unroll
        for (int j = 0; j < 8; j++) {
            s[j][0] *= SCALE; s[j][1] *= SCALE; s[j][2] *= SCALE; s[j][3] *= SCALE;
        }

        float rmax0 = -1e30f, rmax1 = -1e30f;
#pragma unroll
        for (int j = 0; j < 8; j++) {
            rmax0 = fmaxf(rmax0, fmaxf(s[j][0], s[j][1]));
            rmax1 = fmaxf(rmax1, fmaxf(s[j][2], s[j][3]));
        }
        rmax0 = fmaxf(rmax0, __shfl_xor_sync(0xffffffffu, rmax0, 1));
        rmax0 = fmaxf(rmax0, __shfl_xor_sync(0xffffffffu, rmax0, 2));
        rmax1 = fmaxf(rmax1, __shfl_xor_sync(0xffffffffu, rmax1, 1));
        rmax1 = fmaxf(rmax1, __shfl_xor_sync(0xffffffffu, rmax1, 2));

        float mn0 = fmaxf(m0, rmax0), mn1 = fmaxf(m1, rmax1);
        float c0 = __expf(m0 - mn0), c1 = __expf(m1 - mn1);
        float sum0 = 0.f, sum1 = 0.f;
        uint32_t pa[4][4];
#pragma unroll
        for (int jj = 0; jj < 4; jj++) {
            float p00 = __expf(s[2 * jj][0] - mn0),     p01 = __expf(s[2 * jj][1] - mn0);
            float p02 = __expf(s[2 * jj][2] - mn1),     p03 = __expf(s[2 * jj][3] - mn1);
            float p10 = __expf(s[2 * jj + 1][0] - mn0), p11 = __expf(s[2 * jj + 1][1] - mn0);
            float p12 = __expf(s[2 * jj + 1][2] - mn1), p13 = __expf(s[2 * jj + 1][3] - mn1);
            sum0 += p00 + p01 + p10 + p11;
            sum1 += p02 + p03 + p12 + p13;
            pa[jj][0] = packbf(p00, p01);
            pa[jj][1] = packbf(p02, p03);
            pa[jj][2] = packbf(p10, p11);
            pa[jj][3] = packbf(p12, p13);
        }
        sum0 += __shfl_xor_sync(0xffffffffu, sum0, 1);
        sum0 += __shfl_xor_sync(0xffffffffu, sum0, 2);
        sum1 += __shfl_xor_sync(0xffffffffu, sum1, 1);
        sum1 += __shfl_xor_sync(0xffffffffu, sum1, 2);
        l0 = l0 * c0 + sum0;
        l1 = l1 * c1 + sum1;
        m0 = mn0; m1 = mn1;
#pragma unroll
        for (int nt = 0; nt < 4; nt++) {
            o[nt][0] *= c0; o[nt][1] *= c0; o[nt][2] *= c1; o[nt][3] *= c1;
        }

#pragma unroll
        for (int jj = 0; jj < 4; jj++) {
            uint32_t t4[4];
            ldm4t(t4, &Vs[(jj << 4) + (lane & 15)][(lane >> 4) << 3]);
            {
                uint32_t bb0[2] = {t4[0], t4[1]};
                uint32_t bb1[2] = {t4[2], t4[3]};
                mma_bf16(o[0], pa[jj], bb0);
                mma_bf16(o[1], pa[jj], bb1);
            }
            ldm4t(t4, &Vs[(jj << 4) + (lane & 15)][16 + ((lane >> 4) << 3)]);
            {
                uint32_t bb0[2] = {t4[0], t4[1]};
                uint32_t bb1[2] = {t4[2], t4[3]};
                mma_bf16(o[2], pa[jj], bb0);
                mma_bf16(o[3], pa[jj], bb1);
            }
        }
    }

    float inv0 = 1.f / l0, inv1 = 1.f / l1;
    int g = lane >> 2, qd = lane & 3;
    int row0 = q0 + (wid << 4) + g;
#pragma unroll
    for (int nt = 0; nt < 4; nt++) {
        int col = hc + (nt << 3) + (qd << 1);
        uint32_t ph, pl;
        split2(o[nt][0] * inv0, o[nt][1] * inv0, ph, pl);
        *(uint32_t*)&Oh[(size_t)row0 * CM + col] = ph;
        *(uint32_t*)&Ol[(size_t)row0 * CM + col] = pl;
        split2(o[nt][2] * inv1, o[nt][3] * inv1, ph, pl);
        *(uint32_t*)&Oh[(size_t)(row0 + 8) * CM + col] = ph;
        *(uint32_t*)&Ol[(size_t)(row0 + 8) * CM + col] = pl;
    }
}

// ---------------- LayerNorm (optionally emits hi/lo split too) ----------------
template <bool SPLIT>
__global__ void ln_k(const float* __restrict__ X, const float* __restrict__ g,
                     const float* __restrict__ b, float* __restrict__ Y,
                     __nv_bfloat16* __restrict__ Yh, __nv_bfloat16* __restrict__ Yl) {
    int row = blockIdx.x;
    int c = threadIdx.x;
    float v = X[row * CM + c];
    float s = v, s2 = v * v;
#pragma unroll
    for (int o = 16; o > 0; o >>= 1) {
        s += __shfl_xor_sync(0xffffffffu, s, o);
        s2 += __shfl_xor_sync(0xffffffffu, s2, o);
    }
    __shared__ float rs[8], rs2[8];
    int w = c >> 5, lane = c & 31;
    if (lane == 0) { rs[w] = s; rs2[w] = s2; }
    __syncthreads();
    float tot = 0.f, tot2 = 0.f;
#pragma unroll
    for (int i = 0; i < 8; i++) { tot += rs[i]; tot2 += rs2[i]; }
    float mean = tot * (1.f / 256.f);
    float var = tot2 * (1.f / 256.f) - mean * mean;
    float is = rsqrtf(var + 1e-5f);
    float y = (v - mean) * is * g[c] + b[c];
    Y[row * CM + c] = y;
    if (SPLIT) {
        __nv_bfloat16 hh = __float2bfloat16_rn(y);
        Yh[row * CM + c] = hh;
        Yl[row * CM + c] = __float2bfloat16_rn(y - __bfloat162float(hh));
    }
}

// ---------------- launcher ----------------
#define SYM(p, s) cudaGetSymbolAddress((void**)&p, s)

extern "C" void kernel_launch(void* const* d_in, const int* in_sizes, int n_in,
                              void* d_out, int out_size) {
    const float* x_ego  = (const float*)d_in[0];
    const float* x_agent = (const float*)d_in[1];
    const float* Wf1 = (const float*)d_in[2];
    const float* bf1 = (const float*)d_in[3];
    const float* Wf2 = (const float*)d_in[4];
    const float* bf2 = (const float*)d_in[5];
    const float* Wf3 = (const float*)d_in[6];
    const float* bf3 = (const float*)d_in[7];
    const float* Wqkv = (const float*)d_in[8];
    const float* bqkv = (const float*)d_in[9];
    const float* Wo = (const float*)d_in[10];
    const float* bo = (const float*)d_in[11];
    const float* W1 = (const float*)d_in[12];
    const float* b1 = (const float*)d_in[13];
    const float* W2 = (const float*)d_in[14];
    const float* b2 = (const float*)d_in[15];
    const float* g1 = (const float*)d_in[16];
    const float* be1 = (const float*)d_in[17];
    const float* g2 = (const float*)d_in[18];
    const float* be2 = (const float*)d_in[19];
    const int* pos_ego = (const int*)d_in[20];
    const int* pos_agent = (const int*)d_in[21];
    float* out = (float*)d_out;

    float *p_fused, *p_q, *p_res1, *p_yq, *p_res2;
    SYM(p_fused, d_fused); SYM(p_q, d_q); SYM(p_res1, d_res1);
    SYM(p_yq, d_yq); SYM(p_res2, d_res2);

    __nv_bfloat16 *fi_h, *fi_l, *h1_h, *h1_l, *h2_h, *h2_l, *q_h, *q_l, *kv_h, *kv_l;
    __nv_bfloat16 *Qb, *Kb, *Vb, *at_h, *at_l, *yq_h, *yq_l, *ff_h, *ff_l;
    __nv_bfloat16 *wf1_h, *wf1_l, *wf2_h, *wf2_l, *wf3_h, *wf3_l;
    __nv_bfloat16 *wqkv_h, *wqkv_l, *wo_h, *wo_l, *w1_h, *w1_l, *w2_h, *w2_l;
    SYM(fi_h, b_fi_h); SYM(fi_l, b_fi_l);
    SYM(h1_h, b_h1_h); SYM(h1_l, b_h1_l);
    SYM(h2_h, b_h2_h); SYM(h2_l, b_h2_l);
    SYM(q_h, b_q_h); SYM(q_l, b_q_l);
    SYM(kv_h, b_kv_h); SYM(kv_l, b_kv_l);
    SYM(Qb, b_Q); SYM(Kb, b_K); SYM(Vb, b_V);
    SYM(at_h, b_at_h); SYM(at_l, b_at_l);
    SYM(yq_h, b_yq_h); SYM(yq_l, b_yq_l);
    SYM(ff_h, b_ff_h); SYM(ff_l, b_ff_l);
    SYM(wf1_h, b_wf1_h); SYM(wf1_l, b_wf1_l);
    SYM(wf2_h, b_wf2_h); SYM(wf2_l, b_wf2_l);
    SYM(wf3_h, b_wf3_h); SYM(wf3_l, b_wf3_l);
    SYM(wqkv_h, b_wqkv_h); SYM(wqkv_l, b_wqkv_l);
    SYM(wo_h, b_wo_h); SYM(wo_l, b_wo_l);
    SYM(w1_h, b_w1_h); SYM(w1_l, b_w1_l);
    SYM(w2_h, b_w2_h); SYM(w2_l, b_w2_l);

    // 1) weight splits (one kernel, 1,048,576 elements exactly)
    WS ws;
    ws.s[0] = Wf1;  ws.h[0] = wf1_h;  ws.l[0] = wf1_l;
    ws.s[1] = Wf2;  ws.h[1] = wf2_h;  ws.l[1] = wf2_l;
    ws.s[2] = Wf3;  ws.h[2] = wf3_h;  ws.l[2] = wf3_l;
    ws.s[3] = Wqkv; ws.h[3] = wqkv_h; ws.l[3] = wqkv_l;
    ws.s[4] = Wo;   ws.h[4] = wo_h;   ws.l[4] = wo_l;
    ws.s[5] = W1;   ws.h[5] = w1_h;   ws.l[5] = w1_l;
    ws.s[6] = W2;   ws.h[6] = w2_h;   ws.l[6] = w2_l;
    ws.off[0] = 0;       ws.off[1] = 131072;  ws.off[2] = 196608; ws.off[3] = 262144;
    ws.off[4] = 458752;  ws.off[5] = 524288;  ws.off[6] = 786432; ws.off[7] = 1048576;
    wsplit_k<<<4096, 256>>>(ws);

    // 2) matching + compaction
    match_k<<<(LE + LA) / 256, 256>>>(pos_ego, pos_agent);
    compact_scan_k<<<1, 1024>>>();

    // 3) fusion MLP (all-in-epilogue splits)
    build_fusedin_k<<<(LE * 2 * CM) / 256, 256>>>(x_ego, x_agent);
    gemm_bs_k<OUT_SPLIT, true, false><<<dim3(CM / 64, LE / 128), 256>>>(
        fi_h, fi_l, wf1_h, wf1_l, bf1, nullptr, nullptr, h1_h, h1_l, LE, CM, 2 * CM);
    gemm_bs_k<OUT_SPLIT, true, false><<<dim3(CM / 64, LE / 128), 256>>>(
        h1_h, h1_l, wf2_h, wf2_l, bf2, nullptr, nullptr, h2_h, h2_l, LE, CM, CM);
    gemm_bs_k<OUT_F32, false, false><<<dim3(CM / 64, LE / 128), 256>>>(
        h2_h, h2_l, wf3_h, wf3_l, bf3, nullptr, p_fused, nullptr, nullptr, LE, CM, CM);

    // 4) assemble sequences (fused gather+split)
    build_q_k<<<(LQ * CM) / 256, 256>>>(x_ego, x_agent);
    build_kv_k<<<(LK * CM) / 256, 256>>>(x_ego, x_agent);

    // 5) projections: Q (bf16 out), K+V merged (N=512, dual out)
    gemm_bs_k<OUT_BF16, false, false><<<dim3(CM / 64, LQ / 128), 256>>>(
        q_h, q_l, wqkv_h, wqkv_l, bqkv, nullptr, nullptr, Qb, nullptr, LQ, CM, CM);
    gemm_bs_k<OUT_KV, false, false><<<dim3(2 * CM / 64, LK / 128), 256>>>(
        kv_h, kv_l, wqkv_h + CM * CM, wqkv_l + CM * CM, bqkv + CM, nullptr,
        nullptr, Kb, Vb, LK, 2 * CM, CM);

    // 6) attention (split-output epilogue)
    attn_mma_k<<<dim3(LQ / 64, HN), 128>>>(Qb, Kb, Vb, at_h, at_l);

    // 7) out-proj + residual, LN1 (emits fp32 + split)
    gemm_bs_k<OUT_F32, false, true><<<dim3(CM / 64, LQ / 128), 256>>>(
        at_h, at_l, wo_h, wo_l, bo, p_q, p_res1, nullptr, nullptr, LQ, CM, CM);
    ln_k<true><<<LQ, 256>>>(p_res1, g1, be1, p_yq, yq_h, yq_l);

    // 8) FFN + residual, LN2
    gemm_bs_k<OUT_SPLIT, true, false><<<dim3(DF / 64, LQ / 128), 256>>>(
        yq_h, yq_l, w1_h, w1_l, b1, nullptr, nullptr, ff_h, ff_l, LQ, DF, CM);
    gemm_bs_k<OUT_F32, false, true><<<dim3(CM / 64, LQ / 128), 256>>>(
        ff_h, ff_l, w2_h, w2_l, b2, p_yq, p_res2, nullptr, nullptr, LQ, CM, DF);
    ln_k<false><<<LQ, 256>>>(p_res2, g2, be2, out, nullptr, nullptr);
}

// round 8
// speedup vs baseline: 5.4288x; 1.2431x over previous
#include <cuda_runtime.h>
#include <cuda_bf16.h>
#include <cstdint>

// ---------------- problem constants ----------------
#define LE 2048
#define LA 2048
#define CM 256          // d_model
#define HN 8            // heads
#define DH 32           // head dim
#define DF 1024         // ffn dim
#define LQ 3072         // 2048 + 1024 remain
#define LK 4096         // 2048 + 2048
#define SCALE 0.17677669529663687f   // 1/sqrt(32)

// ---------------- fp32 scratch ----------------
__device__ float d_fused[LE * CM];
__device__ float d_q[LQ * CM];
__device__ float d_res1[LQ * CM];
__device__ float d_yq[LQ * CM];
__device__ float d_res2[LQ * CM];
__device__ int d_matched[LE];
__device__ int d_afe[LE];
__device__ int d_unmatched[LA];
__device__ int d_remain[LA];

// ---------------- bf16 scratch ----------------
__device__ __nv_bfloat16 b_fi_h[LE * 2 * CM], b_fi_l[LE * 2 * CM];
__device__ __nv_bfloat16 b_h1_h[LE * CM], b_h1_l[LE * CM];
__device__ __nv_bfloat16 b_h2_h[LE * CM], b_h2_l[LE * CM];
__device__ __nv_bfloat16 b_q_h[LQ * CM], b_q_l[LQ * CM];
__device__ __nv_bfloat16 b_kv_h[LK * CM], b_kv_l[LK * CM];
__device__ __nv_bfloat16 b_Q[LQ * CM];
__device__ __nv_bfloat16 b_K[LK * CM];
__device__ __nv_bfloat16 b_V[LK * CM];
__device__ __nv_bfloat16 b_at_h[LQ * CM], b_at_l[LQ * CM];
__device__ __nv_bfloat16 b_yq_h[LQ * CM], b_yq_l[LQ * CM];
__device__ __nv_bfloat16 b_ff_h[LQ * DF], b_ff_l[LQ * DF];
__device__ __nv_bfloat16 b_wf1_h[CM * 2 * CM], b_wf1_l[CM * 2 * CM];
__device__ __nv_bfloat16 b_wf2_h[CM * CM], b_wf2_l[CM * CM];
__device__ __nv_bfloat16 b_wf3_h[CM * CM], b_wf3_l[CM * CM];
__device__ __nv_bfloat16 b_wqkv_h[3 * CM * CM], b_wqkv_l[3 * CM * CM];
__device__ __nv_bfloat16 b_wo_h[CM * CM], b_wo_l[CM * CM];
__device__ __nv_bfloat16 b_w1_h[DF * CM], b_w1_l[DF * CM];
__device__ __nv_bfloat16 b_w2_h[CM * DF], b_w2_l[CM * DF];

// ---------------- helpers ----------------
static __device__ __forceinline__ uint32_t smem_u32(const void* p) {
    return (uint32_t)__cvta_generic_to_shared(p);
}
static __device__ __forceinline__ void ldm4(uint32_t* r, const void* p) {
    uint32_t a = smem_u32(p);
    asm volatile("ldmatrix.sync.aligned.m8n8.x4.shared.b16 {%0,%1,%2,%3}, [%4];\n"
                 : "=r"(r[0]), "=r"(r[1]), "=r"(r[2]), "=r"(r[3]) : "r"(a));
}
static __device__ __forceinline__ void ldm4t(uint32_t* r, const void* p) {
    uint32_t a = smem_u32(p);
    asm volatile("ldmatrix.sync.aligned.m8n8.x4.trans.shared.b16 {%0,%1,%2,%3}, [%4];\n"
                 : "=r"(r[0]), "=r"(r[1]), "=r"(r[2]), "=r"(r[3]) : "r"(a));
}
static __device__ __forceinline__ void mma_bf16(float* c, const uint32_t* a, const uint32_t* b) {
    asm volatile("mma.sync.aligned.m16n8k16.row.col.f32.bf16.bf16.f32 "
                 "{%0,%1,%2,%3}, {%4,%5,%6,%7}, {%8,%9}, {%0,%1,%2,%3};\n"
                 : "+f"(c[0]), "+f"(c[1]), "+f"(c[2]), "+f"(c[3])
                 : "r"(a[0]), "r"(a[1]), "r"(a[2]), "r"(a[3]), "r"(b[0]), "r"(b[1]));
}
static __device__ __forceinline__ uint32_t packbf(float lo, float hi) {
    uint32_t r;
    asm("cvt.rn.bf16x2.f32 %0, %1, %2;" : "=r"(r) : "f"(hi), "f"(lo));
    return r;
}
static __device__ __forceinline__ void split2(float v0, float v1, uint32_t& ph, uint32_t& pl) {
    __nv_bfloat16 h0 = __float2bfloat16_rn(v0), h1 = __float2bfloat16_rn(v1);
    float l0 = v0 - __bfloat162float(h0);
    float l1 = v1 - __bfloat162float(h1);
    ph = ((uint32_t)__bfloat16_as_ushort(h1) << 16) | (uint32_t)__bfloat16_as_ushort(h0);
    pl = packbf(l0, l1);
}
static __device__ __forceinline__ void cpa16(void* dst, const void* src) {
    uint32_t d = smem_u32(dst);
    asm volatile("cp.async.cg.shared.global [%0], [%1], 16;\n" :: "r"(d), "l"(src));
}
static __device__ __forceinline__ void cpacommit() {
    asm volatile("cp.async.commit_group;\n");
}
template <int N>
static __device__ __forceinline__ void cpawait() {
    asm volatile("cp.async.wait_group %0;\n" :: "n"(N));
}

// ---------------- matching (combined) ----------------
__global__ void match_k(const int* __restrict__ pe, const int* __restrict__ pa) {
    int i = blockIdx.x * blockDim.x + threadIdx.x;
    if (i < LE) {
        int p = pe[i];
        int m = 0, a = 0;
        for (int j = 0; j < LA; j++)
            if (pa[j] == p) { m = 1; a = j; break; }
        d_matched[i] = m;
        d_afe[i] = a;
    } else if (i < LE + LA) {
        int j = i - LE;
        int p = pa[j];
        int um = 1;
        for (int k = 0; k < LE; k++)
            if (pe[k] == p) { um = 0; break; }
        d_unmatched[j] = um;
    }
}

// ---------------- parallel compaction ----------------
__global__ void compact_scan_k() {
    __shared__ int wsum[32];
    int t = threadIdx.x;
    int f0 = d_unmatched[2 * t], f1 = d_unmatched[2 * t + 1];
    int s = f0 + f1;
    int lane = t & 31, w = t >> 5;
    int v = s;
#pragma unroll
    for (int o = 1; o < 32; o <<= 1) {
        int n = __shfl_up_sync(0xffffffffu, v, o);
        if (lane >= o) v += n;
    }
    if (lane == 31) wsum[w] = v;
    __syncthreads();
    if (w == 0) {
        int x = wsum[lane];
#pragma unroll
        for (int o = 1; o < 32; o <<= 1) {
            int n = __shfl_up_sync(0xffffffffu, x, o);
            if (lane >= o) x += n;
        }
        wsum[lane] = x;
    }
    __syncthreads();
    int base = (w > 0 ? wsum[w - 1] : 0) + (v - s);
    if (f0) d_remain[base] = 2 * t;
    if (f1) d_remain[base + f0] = 2 * t + 1;
}

// ---------------- one-shot weight split ----------------
struct WS {
    const float* s[7];
    __nv_bfloat16* h[7];
    __nv_bfloat16* l[7];
    int off[8];
};
__global__ void wsplit_k(WS ws) {
    int i = blockIdx.x * blockDim.x + threadIdx.x;
    int r = 0;
#pragma unroll
    for (int j = 1; j < 7; j++)
        if (i >= ws.off[j]) r = j;
    int loc = i - ws.off[r];
    float v = ws.s[r][loc];
    __nv_bfloat16 hh = __float2bfloat16_rn(v);
    ws.h[r][loc] = hh;
    ws.l[r][loc] = __float2bfloat16_rn(v - __bfloat162float(hh));
}

// ---------------- fused builds ----------------
__global__ void build_fusedin_k(const float* __restrict__ xe, const float* __restrict__ xa) {
    int idx = blockIdx.x * blockDim.x + threadIdx.x;
    if (idx >= LE * 2 * CM) return;
    int row = idx >> 9;
    int c = idx & 511;
    float v = (c < CM) ? xe[row * CM + c] : xa[d_afe[row] * CM + (c - CM)];
    __nv_bfloat16 hh = __float2bfloat16_rn(v);
    b_fi_h[idx] = hh;
    b_fi_l[idx] = __float2bfloat16_rn(v - __bfloat162float(hh));
}
__global__ void build_q_k(const float* __restrict__ xe, const float* __restrict__ xa) {
    int idx = blockIdx.x * blockDim.x + threadIdx.x;
    if (idx >= LQ * CM) return;
    int row = idx >> 8;
    int c = idx & 255;
    float v;
    if (row < LE) v = d_matched[row] ? d_fused[idx] : xe[idx];
    else v = xa[d_remain[row - LE] * CM + c];
    d_q[idx] = v;
    __nv_bfloat16 hh = __float2bfloat16_rn(v);
    b_q_h[idx] = hh;
    b_q_l[idx] = __float2bfloat16_rn(v - __bfloat162float(hh));
}
__global__ void build_kv_k(const float* __restrict__ xe, const float* __restrict__ xa) {
    int idx = blockIdx.x * blockDim.x + threadIdx.x;
    if (idx >= LK * CM) return;
    int row = idx >> 8;
    float v = (row < LE) ? xe[idx] : xa[idx - LE * CM];
    __nv_bfloat16 hh = __float2bfloat16_rn(v);
    b_kv_h[idx] = hh;
    b_kv_l[idx] = __float2bfloat16_rn(v - __bfloat162float(hh));
}

// ---------------- split-bf16 tensor-core GEMM, cp.async double-buffered ----------------
// BM=64, BN=64, BK=32, 256 threads (8 warps, warp tile 16x32).
#define OUT_F32 0
#define OUT_SPLIT 1
#define OUT_BF16 2
#define OUT_KV 3
template <int OMODE, bool RELU, bool RESID>
__global__ void gemm_bs_k(const __nv_bfloat16* __restrict__ Ah, const __nv_bfloat16* __restrict__ Al,
                          const __nv_bfloat16* __restrict__ Wh, const __nv_bfloat16* __restrict__ Wl,
                          const float* __restrict__ bias, const float* __restrict__ Rm,
                          float* __restrict__ Cf, __nv_bfloat16* __restrict__ Ch,
                          __nv_bfloat16* __restrict__ Cl, int M, int N, int K) {
    __shared__ __nv_bfloat16 As[2][2][64][40];   // [stage][hi/lo][row][col]
    __shared__ __nv_bfloat16 Ws[2][2][64][40];
    int tid = threadIdx.x, lane = tid & 31, wid = tid >> 5;
    int bm = blockIdx.y << 6, bn = blockIdx.x << 6;
    int wm = (wid >> 1) << 4, wn = (wid & 1) << 5;

    float acc[4][4];
#pragma unroll
    for (int j = 0; j < 4; j++)
#pragma unroll
        for (int k = 0; k < 4; k++) acc[j][k] = 0.f;

    int lr = tid >> 2;             // row 0..63
    int lc = (tid & 3) << 3;       // col chunk 0,8,16,24
    const __nv_bfloat16* gAh = Ah + (size_t)(bm + lr) * K + lc;
    const __nv_bfloat16* gAl = Al + (size_t)(bm + lr) * K + lc;
    const __nv_bfloat16* gWh = Wh + (size_t)(bn + lr) * K + lc;
    const __nv_bfloat16* gWl = Wl + (size_t)(bn + lr) * K + lc;

    int a_r = lane & 15, a_c = (lane >> 4) << 3;
    int b_r = (lane & 7) + ((lane >> 4) << 3), b_c = ((lane >> 3) & 1) << 3;
    int KT = K >> 5;

    // preload stage 0
    {
        cpa16(&As[0][0][lr][lc], gAh);
        cpa16(&As[0][1][lr][lc], gAl);
        cpa16(&Ws[0][0][lr][lc], gWh);
        cpa16(&Ws[0][1][lr][lc], gWl);
        cpacommit();
    }

    for (int kt = 0; kt < KT; kt++) {
        int cur = kt & 1;
        if (kt + 1 < KT) {
            int k0 = (kt + 1) << 5;
            int nx = cur ^ 1;
            cpa16(&As[nx][0][lr][lc], gAh + k0);
            cpa16(&As[nx][1][lr][lc], gAl + k0);
            cpa16(&Ws[nx][0][lr][lc], gWh + k0);
            cpa16(&Ws[nx][1][lr][lc], gWl + k0);
            cpacommit();
            cpawait<1>();
        } else {
            cpawait<0>();
        }
        __syncthreads();
#pragma unroll
        for (int ks = 0; ks < 2; ks++) {
            uint32_t ah[4], al[4], bh[4][2], bl[4][2];
            ldm4(ah, &As[cur][0][wm + a_r][(ks << 4) + a_c]);
            ldm4(al, &As[cur][1][wm + a_r][(ks << 4) + a_c]);
#pragma unroll
            for (int np = 0; np < 2; np++) {
                uint32_t t4[4];
                ldm4(t4, &Ws[cur][0][wn + (np << 4) + b_r][(ks << 4) + b_c]);
                bh[np * 2][0] = t4[0]; bh[np * 2][1] = t4[1];
                bh[np * 2 + 1][0] = t4[2]; bh[np * 2 + 1][1] = t4[3];
                ldm4(t4, &Ws[cur][1][wn + (np << 4) + b_r][(ks << 4) + b_c]);
                bl[np * 2][0] = t4[0]; bl[np * 2][1] = t4[1];
                bl[np * 2 + 1][0] = t4[2]; bl[np * 2 + 1][1] = t4[3];
            }
#pragma unroll
            for (int nt = 0; nt < 4; nt++) {
                mma_bf16(acc[nt], ah, bh[nt]);
                mma_bf16(acc[nt], ah, bl[nt]);
                mma_bf16(acc[nt], al, bh[nt]);
            }
        }
        __syncthreads();
    }

    int g = lane >> 2, qd = lane & 3;
    int r0 = bm + wm + g;
#pragma unroll
    for (int nt = 0; nt < 4; nt++) {
        int col = bn + wn + (nt << 3) + (qd << 1);
        float b0 = bias[col], b1 = bias[col + 1];
        float v0 = acc[nt][0] + b0, v1 = acc[nt][1] + b1;
        float v2 = acc[nt][2] + b0, v3 = acc[nt][3] + b1;
        if (RESID) {
            v0 += Rm[(size_t)r0 * N + col];       v1 += Rm[(size_t)r0 * N + col + 1];
            v2 += Rm[(size_t)(r0 + 8) * N + col]; v3 += Rm[(size_t)(r0 + 8) * N + col + 1];
        }
        if (RELU) {
            v0 = fmaxf(v0, 0.f); v1 = fmaxf(v1, 0.f);
            v2 = fmaxf(v2, 0.f); v3 = fmaxf(v3, 0.f);
        }
        size_t i0 = (size_t)r0 * N + col, i1 = (size_t)(r0 + 8) * N + col;
        if (OMODE == OUT_F32) {
            *(float2*)&Cf[i0] = make_float2(v0, v1);
            *(float2*)&Cf[i1] = make_float2(v2, v3);
        } else if (OMODE == OUT_BF16) {
            *(uint32_t*)&Ch[i0] = packbf(v0, v1);
            *(uint32_t*)&Ch[i1] = packbf(v2, v3);
        } else if (OMODE == OUT_SPLIT) {
            uint32_t ph, pl;
            split2(v0, v1, ph, pl);
            *(uint32_t*)&Ch[i0] = ph; *(uint32_t*)&Cl[i0] = pl;
            split2(v2, v3, ph, pl);
            *(uint32_t*)&Ch[i1] = ph; *(uint32_t*)&Cl[i1] = pl;
        } else {  // OUT_KV
            __nv_bfloat16* dst = (col < CM) ? Ch : Cl;
            int cc = col & (CM - 1);
            *(uint32_t*)&dst[(size_t)r0 * CM + cc] = packbf(v0, v1);
            *(uint32_t*)&dst[(size_t)(r0 + 8) * CM + cc] = packbf(v2, v3);
        }
    }
}

// ---------------- flash attention, cp.async double-buffered kv tiles ----------------
__global__ void attn_mma_k(const __nv_bfloat16* __restrict__ Qb, const __nv_bfloat16* __restrict__ Kb,
                           const __nv_bfloat16* __restrict__ Vb,
                           __nv_bfloat16* __restrict__ Oh, __nv_bfloat16* __restrict__ Ol) {
    __shared__ __nv_bfloat16 Qs[64][40];
    __shared__ __nv_bfloat16 Ks[2][64][40];
    __shared__ __nv_bfloat16 Vs[2][64][40];
    int tid = threadIdx.x, lane = tid & 31, wid = tid >> 5;
    int h = blockIdx.y, q0 = blockIdx.x << 6;
    int hc = h << 5;

    int ldr = tid >> 1, ldc = (tid & 1) << 4;   // row 0..63, col 0/16

    // preload kv tile 0 (async) before Q staging
    {
        const __nv_bfloat16* pk = Kb + (size_t)ldr * CM + hc + ldc;
        const __nv_bfloat16* pv = Vb + (size_t)ldr * CM + hc + ldc;
        cpa16(&Ks[0][ldr][ldc], pk);
        cpa16(&Ks[0][ldr][ldc + 8], pk + 8);
        cpa16(&Vs[0][ldr][ldc], pv);
        cpa16(&Vs[0][ldr][ldc + 8], pv + 8);
        cpacommit();
    }
    {
        const uint4* p = (const uint4*)(Qb + (size_t)(q0 + ldr) * CM + hc + ldc);
        *(uint4*)&Qs[ldr][ldc] = p[0];
        *(uint4*)&Qs[ldr][ldc + 8] = p[1];
    }
    __syncthreads();

    int a_r = lane & 15, a_c = (lane >> 4) << 3;
    uint32_t qf[2][4];
    ldm4(qf[0], &Qs[(wid << 4) + a_r][a_c]);
    ldm4(qf[1], &Qs[(wid << 4) + a_r][16 + a_c]);

    float o[4][4];
#pragma unroll
    for (int i = 0; i < 4; i++)
#pragma unroll
        for (int j = 0; j < 4; j++) o[i][j] = 0.f;
    float m0 = -1e30f, m1 = -1e30f, l0 = 0.f, l1 = 0.f;

    int b_r = (lane & 7) + ((lane >> 4) << 3), b_c = ((lane >> 3) & 1) << 3;
    int NT = LK / 64;

    for (int t = 0; t < NT; t++) {
        int cur = t & 1;
        if (t + 1 < NT) {
            int nx = cur ^ 1;
            const __nv_bfloat16* pk = Kb + (size_t)((t + 1) * 64 + ldr) * CM + hc + ldc;
            const __nv_bfloat16* pv = Vb + (size_t)((t + 1) * 64 + ldr) * CM + hc + ldc;
            cpa16(&Ks[nx][ldr][ldc], pk);
            cpa16(&Ks[nx][ldr][ldc + 8], pk + 8);
            cpa16(&Vs[nx][ldr][ldc], pv);
            cpa16(&Vs[nx][ldr][ldc + 8], pv + 8);
            cpacommit();
            cpawait<1>();
        } else {
            cpawait<0>();
        }
        __syncthreads();

        float s[8][4];
#pragma unroll
        for (int j = 0; j < 8; j++)
#pragma unroll
            for (int c = 0; c < 4; c++) s[j][c] = 0.f;
#pragma unroll
        for (int ks = 0; ks < 2; ks++) {
#pragma unroll
            for (int jp = 0; jp < 4; jp++) {
                uint32_t t4[4];
                ldm4(t4, &Ks[cur][(jp << 4) + b_r][(ks << 4) + b_c]);
                uint32_t bb0[2] = {t4[0], t4[1]};
                uint32_t bb1[2] = {t4[2], t4[3]};
                mma_bf16(s[jp * 2], qf[ks], bb0);
                mma_bf16(s[jp * 2 + 1], qf[ks], bb1);
            }
        }
#pragma unroll
        for (int j = 0; j < 8; j++) {
            s[j][0] *= SCALE; s[j][1] *= SCALE; s[j][2] *= SCALE; s[j][3] *= SCALE;
        }

        float rmax0 = -1e30f, rmax1 = -1e30f;
#pragma unroll
        for (int j = 0; j < 8; j++) {
            rmax0 = fmaxf(rmax0, fmaxf(s[j][0], s[j][1]));
            rmax1 = fmaxf(rmax1, fmaxf(s[j][2], s[j][3]));
        }
        rmax0 = fmaxf(rmax0, __shfl_xor_sync(0xffffffffu, rmax0, 1));
        rmax0 = fmaxf(rmax0, __shfl_xor_sync(0xffffffffu, rmax0, 2));
        rmax1 = fmaxf(rmax1, __shfl_xor_sync(0xffffffffu, rmax1, 1));
        rmax1 = fmaxf(rmax1, __shfl_xor_sync(0xffffffffu, rmax1, 2));

        float mn0 = fmaxf(m0, rmax0), mn1 = fmaxf(m1, rmax1);
        float c0 = __expf(m0 - mn0), c1 = __expf(m1 - mn1);
        float sum0 = 0.f, sum1 = 0.f;
        uint32_t pa[4][4];
#pragma unroll
        for (int jj = 0; jj < 4; jj++) {
            float p00 = __expf(s[2 * jj][0] - mn0),     p01 = __expf(s[2 * jj][1] - mn0);
            float p02 = __expf(s[2 * jj][2] - mn1),     p03 = __expf(s[2 * jj][3] - mn1);
            float p10 = __expf(s[2 * jj + 1][0] - mn0), p11 = __expf(s[2 * jj + 1][1] - mn0);
            float p12 = __expf(s[2 * jj + 1][2] - mn1), p13 = __expf(s[2 * jj + 1][3] - mn1);
            sum0 += p00 + p01 + p10 + p11;
            sum1 += p02 + p03 + p12 + p13;
            pa[jj][0] = packbf(p00, p01);
            pa[jj][1] = packbf(p02, p03);
            pa[jj][2] = packbf(p10, p11);
            pa[jj][3] = packbf(p12, p13);
        }
        sum0 += __shfl_xor_sync(0xffffffffu, sum0, 1);
        sum0 += __shfl_xor_sync(0xffffffffu, sum0, 2);
        sum1 += __shfl_xor_sync(0xffffffffu, sum1, 1);
        sum1 += __shfl_xor_sync(0xffffffffu, sum1, 2);
        l0 = l0 * c0 + sum0;
        l1 = l1 * c1 + sum1;
        m0 = mn0; m1 = mn1;
#pragma unroll
        for (int nt = 0; nt < 4; nt++) {
            o[nt][0] *= c0; o[nt][1] *= c0; o[nt][2] *= c1; o[nt][3] *= c1;
        }

#pragma unroll
        for (int jj = 0; jj < 4; jj++) {
            uint32_t t4[4];
            ldm4t(t4, &Vs[cur][(jj << 4) + (lane & 15)][(lane >> 4) << 3]);
            {
                uint32_t bb0[2] = {t4[0], t4[1]};
                uint32_t bb1[2] = {t4[2], t4[3]};
                mma_bf16(o[0], pa[jj], bb0);
                mma_bf16(o[1], pa[jj], bb1);
            }
            ldm4t(t4, &Vs[cur][(jj << 4) + (lane & 15)][16 + ((lane >> 4) << 3)]);
            {
                uint32_t bb0[2] = {t4[0], t4[1]};
                uint32_t bb1[2] = {t4[2], t4[3]};
                mma_bf16(o[2], pa[jj], bb0);
                mma_bf16(o[3], pa[jj], bb1);
            }
        }
        __syncthreads();
    }

    float inv0 = 1.f / l0, inv1 = 1.f / l1;
    int g = lane >> 2, qd = lane & 3;
    int row0 = q0 + (wid << 4) + g;
#pragma unroll
    for (int nt = 0; nt < 4; nt++) {
        int col = hc + (nt << 3) + (qd << 1);
        uint32_t ph, pl;
        split2(o[nt][0] * inv0, o[nt][1] * inv0, ph, pl);
        *(uint32_t*)&Oh[(size_t)row0 * CM + col] = ph;
        *(uint32_t*)&Ol[(size_t)row0 * CM + col] = pl;
        split2(o[nt][2] * inv1, o[nt][3] * inv1, ph, pl);
        *(uint32_t*)&Oh[(size_t)(row0 + 8) * CM + col] = ph;
        *(uint32_t*)&Ol[(size_t)(row0 + 8) * CM + col] = pl;
    }
}

// ---------------- LayerNorm ----------------
template <bool SPLIT>
__global__ void ln_k(const float* __restrict__ X, const float* __restrict__ g,
                     const float* __restrict__ b, float* __restrict__ Y,
                     __nv_bfloat16* __restrict__ Yh, __nv_bfloat16* __restrict__ Yl) {
    int row = blockIdx.x;
    int c = threadIdx.x;
    float v = X[row * CM + c];
    float s = v, s2 = v * v;
#pragma unroll
    for (int o = 16; o > 0; o >>= 1) {
        s += __shfl_xor_sync(0xffffffffu, s, o);
        s2 += __shfl_xor_sync(0xffffffffu, s2, o);
    }
    __shared__ float rs[8], rs2[8];
    int w = c >> 5, lane = c & 31;
    if (lane == 0) { rs[w] = s; rs2[w] = s2; }
    __syncthreads();
    float tot = 0.f, tot2 = 0.f;
#pragma unroll
    for (int i = 0; i < 8; i++) { tot += rs[i]; tot2 += rs2[i]; }
    float mean = tot * (1.f / 256.f);
    float var = tot2 * (1.f / 256.f) - mean * mean;
    float is = rsqrtf(var + 1e-5f);
    float y = (v - mean) * is * g[c] + b[c];
    Y[row * CM + c] = y;
    if (SPLIT) {
        __nv_bfloat16 hh = __float2bfloat16_rn(y);
        Yh[row * CM + c] = hh;
        Yl[row * CM + c] = __float2bfloat16_rn(y - __bfloat162float(hh));
    }
}

// ---------------- launcher ----------------
#define SYM(p, s) cudaGetSymbolAddress((void**)&p, s)

extern "C" void kernel_launch(void* const* d_in, const int* in_sizes, int n_in,
                              void* d_out, int out_size) {
    const float* x_ego  = (const float*)d_in[0];
    const float* x_agent = (const float*)d_in[1];
    const float* Wf1 = (const float*)d_in[2];
    const float* bf1 = (const float*)d_in[3];
    const float* Wf2 = (const float*)d_in[4];
    const float* bf2 = (const float*)d_in[5];
    const float* Wf3 = (const float*)d_in[6];
    const float* bf3 = (const float*)d_in[7];
    const float* Wqkv = (const float*)d_in[8];
    const float* bqkv = (const float*)d_in[9];
    const float* Wo = (const float*)d_in[10];
    const float* bo = (const float*)d_in[11];
    const float* W1 = (const float*)d_in[12];
    const float* b1 = (const float*)d_in[13];
    const float* W2 = (const float*)d_in[14];
    const float* b2 = (const float*)d_in[15];
    const float* g1 = (const float*)d_in[16];
    const float* be1 = (const float*)d_in[17];
    const float* g2 = (const float*)d_in[18];
    const float* be2 = (const float*)d_in[19];
    const int* pos_ego = (const int*)d_in[20];
    const int* pos_agent = (const int*)d_in[21];
    float* out = (float*)d_out;

    float *p_fused, *p_q, *p_res1, *p_yq, *p_res2;
    SYM(p_fused, d_fused); SYM(p_q, d_q); SYM(p_res1, d_res1);
    SYM(p_yq, d_yq); SYM(p_res2, d_res2);

    __nv_bfloat16 *fi_h, *fi_l, *h1_h, *h1_l, *h2_h, *h2_l, *q_h, *q_l, *kv_h, *kv_l;
    __nv_bfloat16 *Qb, *Kb, *Vb, *at_h, *at_l, *yq_h, *yq_l, *ff_h, *ff_l;
    __nv_bfloat16 *wf1_h, *wf1_l, *wf2_h, *wf2_l, *wf3_h, *wf3_l;
    __nv_bfloat16 *wqkv_h, *wqkv_l, *wo_h, *wo_l, *w1_h, *w1_l, *w2_h, *w2_l;
    SYM(fi_h, b_fi_h); SYM(fi_l, b_fi_l);
    SYM(h1_h, b_h1_h); SYM(h1_l, b_h1_l);
    SYM(h2_h, b_h2_h); SYM(h2_l, b_h2_l);
    SYM(q_h, b_q_h); SYM(q_l, b_q_l);
    SYM(kv_h, b_kv_h); SYM(kv_l, b_kv_l);
    SYM(Qb, b_Q); SYM(Kb, b_K); SYM(Vb, b_V);
    SYM(at_h, b_at_h); SYM(at_l, b_at_l);
    SYM(yq_h, b_yq_h); SYM(yq_l, b_yq_l);
    SYM(ff_h, b_ff_h); SYM(ff_l, b_ff_l);
    SYM(wf1_h, b_wf1_h); SYM(wf1_l, b_wf1_l);
    SYM(wf2_h, b_wf2_h); SYM(wf2_l, b_wf2_l);
    SYM(wf3_h, b_wf3_h); SYM(wf3_l, b_wf3_l);
    SYM(wqkv_h, b_wqkv_h); SYM(wqkv_l, b_wqkv_l);
    SYM(wo_h, b_wo_h); SYM(wo_l, b_wo_l);
    SYM(w1_h, b_w1_h); SYM(w1_l, b_w1_l);
    SYM(w2_h, b_w2_h); SYM(w2_l, b_w2_l);

    // streams/events for fork-join graph branches (host objects, created once)
    static cudaStream_t sA = nullptr, sB = nullptr;
    static cudaEvent_t ev0, ev1, ev2;
    if (!sA) {
        cudaStreamCreateWithFlags(&sA, cudaStreamNonBlocking);
        cudaStreamCreateWithFlags(&sB, cudaStreamNonBlocking);
        cudaEventCreateWithFlags(&ev0, cudaEventDisableTiming);
        cudaEventCreateWithFlags(&ev1, cudaEventDisableTiming);
        cudaEventCreateWithFlags(&ev2, cudaEventDisableTiming);
    }

    WS ws;
    ws.s[0] = Wf1;  ws.h[0] = wf1_h;  ws.l[0] = wf1_l;
    ws.s[1] = Wf2;  ws.h[1] = wf2_h;  ws.l[1] = wf2_l;
    ws.s[2] = Wf3;  ws.h[2] = wf3_h;  ws.l[2] = wf3_l;
    ws.s[3] = Wqkv; ws.h[3] = wqkv_h; ws.l[3] = wqkv_l;
    ws.s[4] = Wo;   ws.h[4] = wo_h;   ws.l[4] = wo_l;
    ws.s[5] = W1;   ws.h[5] = w1_h;   ws.l[5] = w1_l;
    ws.s[6] = W2;   ws.h[6] = w2_h;   ws.l[6] = w2_l;
    ws.off[0] = 0;       ws.off[1] = 131072;  ws.off[2] = 196608; ws.off[3] = 262144;
    ws.off[4] = 458752;  ws.off[5] = 524288;  ws.off[6] = 786432; ws.off[7] = 1048576;

    // fork point
    cudaEventRecord(ev0, 0);

    // branch A: weight splits
    cudaStreamWaitEvent(sA, ev0, 0);
    wsplit_k<<<4096, 256, 0, sA>>>(ws);
    cudaEventRecord(ev1, sA);

    // branch B: kv build + K/V projection (needs weights)
    cudaStreamWaitEvent(sB, ev0, 0);
    build_kv_k<<<(LK * CM) / 256, 256, 0, sB>>>(x_ego, x_agent);
    cudaStreamWaitEvent(sB, ev1, 0);
    gemm_bs_k<OUT_KV, false, false><<<dim3(2 * CM / 64, LK / 64), 256, 0, sB>>>(
        kv_h, kv_l, wqkv_h + CM * CM, wqkv_l + CM * CM, bqkv + CM, nullptr,
        nullptr, Kb, Vb, LK, 2 * CM, CM);
    cudaEventRecord(ev2, sB);

    // main branch: matching, fusion MLP, Q path
    match_k<<<(LE + LA) / 256, 256>>>(pos_ego, pos_agent);
    compact_scan_k<<<1, 1024>>>();
    build_fusedin_k<<<(LE * 2 * CM) / 256, 256>>>(x_ego, x_agent);
    cudaStreamWaitEvent(0, ev1, 0);
    gemm_bs_k<OUT_SPLIT, true, false><<<dim3(CM / 64, LE / 64), 256>>>(
        fi_h, fi_l, wf1_h, wf1_l, bf1, nullptr, nullptr, h1_h, h1_l, LE, CM, 2 * CM);
    gemm_bs_k<OUT_SPLIT, true, false><<<dim3(CM / 64, LE / 64), 256>>>(
        h1_h, h1_l, wf2_h, wf2_l, bf2, nullptr, nullptr, h2_h, h2_l, LE, CM, CM);
    gemm_bs_k<OUT_F32, false, false><<<dim3(CM / 64, LE / 64), 256>>>(
        h2_h, h2_l, wf3_h, wf3_l, bf3, nullptr, p_fused, nullptr, nullptr, LE, CM, CM);
    build_q_k<<<(LQ * CM) / 256, 256>>>(x_ego, x_agent);
    gemm_bs_k<OUT_BF16, false, false><<<dim3(CM / 64, LQ / 64), 256>>>(
        q_h, q_l, wqkv_h, wqkv_l, bqkv, nullptr, nullptr, Qb, nullptr, LQ, CM, CM);

    // join: attention needs K/V from branch B
    cudaStreamWaitEvent(0, ev2, 0);
    attn_mma_k<<<dim3(LQ / 64, HN), 128>>>(Qb, Kb, Vb, at_h, at_l);

    gemm_bs_k<OUT_F32, false, true><<<dim3(CM / 64, LQ / 64), 256>>>(
        at_h, at_l, wo_h, wo_l, bo, p_q, p_res1, nullptr, nullptr, LQ, CM, CM);
    ln_k<true><<<LQ, 256>>>(p_res1, g1, be1, p_yq, yq_h, yq_l);
    gemm_bs_k<OUT_SPLIT, true, false><<<dim3(DF / 64, LQ / 64), 256>>>(
        yq_h, yq_l, w1_h, w1_l, b1, nullptr, nullptr, ff_h, ff_l, LQ, DF, CM);
    gemm_bs_k<OUT_F32, false, true><<<dim3(CM / 64, LQ / 64), 256>>>(
        ff_h, ff_l, w2_h, w2_l, b2, p_yq, p_res2, nullptr, nullptr, LQ, CM, DF);
    ln_k<false><<<LQ, 256>>>(p_res2, g2, be2, out, nullptr, nullptr);
}

// round 9
// speedup vs baseline: 7.0431x; 1.2974x over previous
#include <cuda_runtime.h>
#include <cuda_bf16.h>
#include <cstdint>

// ---------------- problem constants ----------------
#define LE 2048
#define LA 2048
#define CM 256          // d_model
#define HN 8            // heads
#define DH 32           // head dim
#define DF 1024         // ffn dim
#define LQ 3072         // 2048 + 1024 remain
#define LK 4096         // 2048 + 2048
#define SCALE 0.17677669529663687f   // 1/sqrt(32)

#define HT_SIZE 4096
#define HT_MASK (HT_SIZE - 1)
#define HT_EMPTY 0xFFFFFFFFFFFFFFFFull

// ---------------- fp32 scratch ----------------
__device__ float d_fused[LE * CM];
__device__ float d_q[LQ * CM];
__device__ float d_res1[LQ * CM];
__device__ float d_yq[LQ * CM];
__device__ float d_res2[LQ * CM];
__device__ int d_matched[LE];
__device__ int d_afe[LE];
__device__ int d_unmatched[LA];
__device__ int d_remain[LA];
__device__ unsigned long long d_ht[HT_SIZE];

// ---------------- bf16 scratch ----------------
__device__ __nv_bfloat16 b_fi_h[LE * 2 * CM], b_fi_l[LE * 2 * CM];
__device__ __nv_bfloat16 b_h1_h[LE * CM], b_h1_l[LE * CM];
__device__ __nv_bfloat16 b_h2_h[LE * CM], b_h2_l[LE * CM];
__device__ __nv_bfloat16 b_q_h[LQ * CM], b_q_l[LQ * CM];
__device__ __nv_bfloat16 b_kv_h[LK * CM], b_kv_l[LK * CM];
__device__ __nv_bfloat16 b_Q[LQ * CM];
__device__ __nv_bfloat16 b_K[LK * CM];
__device__ __nv_bfloat16 b_V[LK * CM];
__device__ __nv_bfloat16 b_at_h[LQ * CM], b_at_l[LQ * CM];
__device__ __nv_bfloat16 b_yq_h[LQ * CM], b_yq_l[LQ * CM];
__device__ __nv_bfloat16 b_ff_h[LQ * DF], b_ff_l[LQ * DF];
__device__ __nv_bfloat16 b_wf1_h[CM * 2 * CM], b_wf1_l[CM * 2 * CM];
__device__ __nv_bfloat16 b_wf2_h[CM * CM], b_wf2_l[CM * CM];
__device__ __nv_bfloat16 b_wf3_h[CM * CM], b_wf3_l[CM * CM];
__device__ __nv_bfloat16 b_wqkv_h[3 * CM * CM], b_wqkv_l[3 * CM * CM];
__device__ __nv_bfloat16 b_wo_h[CM * CM], b_wo_l[CM * CM];
__device__ __nv_bfloat16 b_w1_h[DF * CM], b_w1_l[DF * CM];
__device__ __nv_bfloat16 b_w2_h[CM * DF], b_w2_l[CM * DF];

// ---------------- helpers ----------------
static __device__ __forceinline__ uint32_t smem_u32(const void* p) {
    return (uint32_t)__cvta_generic_to_shared(p);
}
static __device__ __forceinline__ void ldm4(uint32_t* r, const void* p) {
    uint32_t a = smem_u32(p);
    asm volatile("ldmatrix.sync.aligned.m8n8.x4.shared.b16 {%0,%1,%2,%3}, [%4];\n"
                 : "=r"(r[0]), "=r"(r[1]), "=r"(r[2]), "=r"(r[3]) : "r"(a));
}
static __device__ __forceinline__ void ldm4t(uint32_t* r, const void* p) {
    uint32_t a = smem_u32(p);
    asm volatile("ldmatrix.sync.aligned.m8n8.x4.trans.shared.b16 {%0,%1,%2,%3}, [%4];\n"
                 : "=r"(r[0]), "=r"(r[1]), "=r"(r[2]), "=r"(r[3]) : "r"(a));
}
static __device__ __forceinline__ void mma_bf16(float* c, const uint32_t* a, const uint32_t* b) {
    asm volatile("mma.sync.aligned.m16n8k16.row.col.f32.bf16.bf16.f32 "
                 "{%0,%1,%2,%3}, {%4,%5,%6,%7}, {%8,%9}, {%0,%1,%2,%3};\n"
                 : "+f"(c[0]), "+f"(c[1]), "+f"(c[2]), "+f"(c[3])
                 : "r"(a[0]), "r"(a[1]), "r"(a[2]), "r"(a[3]), "r"(b[0]), "r"(b[1]));
}
static __device__ __forceinline__ uint32_t packbf(float lo, float hi) {
    uint32_t r;
    asm("cvt.rn.bf16x2.f32 %0, %1, %2;" : "=r"(r) : "f"(hi), "f"(lo));
    return r;
}
static __device__ __forceinline__ void split2(float v0, float v1, uint32_t& ph, uint32_t& pl) {
    __nv_bfloat16 h0 = __float2bfloat16_rn(v0), h1 = __float2bfloat16_rn(v1);
    float l0 = v0 - __bfloat162float(h0);
    float l1 = v1 - __bfloat162float(h1);
    ph = ((uint32_t)__bfloat16_as_ushort(h1) << 16) | (uint32_t)__bfloat16_as_ushort(h0);
    pl = packbf(l0, l1);
}
static __device__ __forceinline__ void cpa16(void* dst, const void* src) {
    uint32_t d = smem_u32(dst);
    asm volatile("cp.async.cg.shared.global [%0], [%1], 16;\n" :: "r"(d), "l"(src));
}
static __device__ __forceinline__ void cpacommit() {
    asm volatile("cp.async.commit_group;\n");
}
template <int N>
static __device__ __forceinline__ void cpawait() {
    asm volatile("cp.async.wait_group %0;\n" :: "n"(N));
}
static __device__ __forceinline__ uint32_t ht_hash(uint32_t k) {
    return (k * 2654435761u) & HT_MASK;
}

// ---------------- hash-table matching ----------------
__global__ void ht_init_k() {
    int i = blockIdx.x * blockDim.x + threadIdx.x;
    if (i < HT_SIZE) d_ht[i] = HT_EMPTY;
}
__global__ void ht_insert_k(const int* __restrict__ pa) {
    int j = blockIdx.x * blockDim.x + threadIdx.x;
    if (j >= LA) return;
    d_unmatched[j] = 1;
    uint32_t key = (uint32_t)pa[j];
    unsigned long long entry = ((unsigned long long)key << 32) | (uint32_t)j;
    uint32_t h = ht_hash(key);
    while (true) {
        unsigned long long prev = atomicCAS(&d_ht[h], HT_EMPTY, entry);
        if (prev == HT_EMPTY) break;
        h = (h + 1) & HT_MASK;
    }
}
__global__ void ht_lookup_k(const int* __restrict__ pe) {
    int i = blockIdx.x * blockDim.x + threadIdx.x;
    if (i >= LE) return;
    uint32_t key = (uint32_t)pe[i];
    uint32_t h = ht_hash(key);
    int m = 0, a = 0;
    while (true) {
        unsigned long long e = d_ht[h];
        if (e == HT_EMPTY) break;
        if ((uint32_t)(e >> 32) == key) { m = 1; a = (int)(uint32_t)e; break; }
        h = (h + 1) & HT_MASK;
    }
    d_matched[i] = m;
    d_afe[i] = a;
    if (m) d_unmatched[a] = 0;   // bijection on unique values: distinct a per i
}

// ---------------- parallel compaction ----------------
__global__ void compact_scan_k() {
    __shared__ int wsum[32];
    int t = threadIdx.x;
    int f0 = d_unmatched[2 * t], f1 = d_unmatched[2 * t + 1];
    int s = f0 + f1;
    int lane = t & 31, w = t >> 5;
    int v = s;
#pragma unroll
    for (int o = 1; o < 32; o <<= 1) {
        int n = __shfl_up_sync(0xffffffffu, v, o);
        if (lane >= o) v += n;
    }
    if (lane == 31) wsum[w] = v;
    __syncthreads();
    if (w == 0) {
        int x = wsum[lane];
#pragma unroll
        for (int o = 1; o < 32; o <<= 1) {
            int n = __shfl_up_sync(0xffffffffu, x, o);
            if (lane >= o) x += n;
        }
        wsum[lane] = x;
    }
    __syncthreads();
    int base = (w > 0 ? wsum[w - 1] : 0) + (v - s);
    if (f0) d_remain[base] = 2 * t;
    if (f1) d_remain[base + f0] = 2 * t + 1;
}

// ---------------- one-shot weight split ----------------
struct WS {
    const float* s[7];
    __nv_bfloat16* h[7];
    __nv_bfloat16* l[7];
    int off[8];
};
__global__ void wsplit_k(WS ws) {
    int i = blockIdx.x * blockDim.x + threadIdx.x;
    int r = 0;
#pragma unroll
    for (int j = 1; j < 7; j++)
        if (i >= ws.off[j]) r = j;
    int loc = i - ws.off[r];
    float v = ws.s[r][loc];
    __nv_bfloat16 hh = __float2bfloat16_rn(v);
    ws.h[r][loc] = hh;
    ws.l[r][loc] = __float2bfloat16_rn(v - __bfloat162float(hh));
}

// ---------------- fused builds ----------------
__global__ void build_fusedin_k(const float* __restrict__ xe, const float* __restrict__ xa) {
    int idx = blockIdx.x * blockDim.x + threadIdx.x;
    if (idx >= LE * 2 * CM) return;
    int row = idx >> 9;
    int c = idx & 511;
    float v = (c < CM) ? xe[row * CM + c] : xa[d_afe[row] * CM + (c - CM)];
    __nv_bfloat16 hh = __float2bfloat16_rn(v);
    b_fi_h[idx] = hh;
    b_fi_l[idx] = __float2bfloat16_rn(v - __bfloat162float(hh));
}
__global__ void build_q_k(const float* __restrict__ xe, const float* __restrict__ xa) {
    int idx = blockIdx.x * blockDim.x + threadIdx.x;
    if (idx >= LQ * CM) return;
    int row = idx >> 8;
    int c = idx & 255;
    float v;
    if (row < LE) v = d_matched[row] ? d_fused[idx] : xe[idx];
    else v = xa[d_remain[row - LE] * CM + c];
    d_q[idx] = v;
    __nv_bfloat16 hh = __float2bfloat16_rn(v);
    b_q_h[idx] = hh;
    b_q_l[idx] = __float2bfloat16_rn(v - __bfloat162float(hh));
}
__global__ void build_kv_k(const float* __restrict__ xe, const float* __restrict__ xa) {
    int idx = blockIdx.x * blockDim.x + threadIdx.x;
    if (idx >= LK * CM) return;
    int row = idx >> 8;
    float v = (row < LE) ? xe[idx] : xa[idx - LE * CM];
    __nv_bfloat16 hh = __float2bfloat16_rn(v);
    b_kv_h[idx] = hh;
    b_kv_l[idx] = __float2bfloat16_rn(v - __bfloat162float(hh));
}

// ---------------- split-bf16 tensor-core GEMM, cp.async double-buffered ----------------
// BM=64, BN=64, BK=32, 256 threads (8 warps, warp tile 16x32).
#define OUT_F32 0
#define OUT_SPLIT 1
#define OUT_BF16 2
#define OUT_KV 3
template <int OMODE, bool RELU, bool RESID>
__global__ void gemm_bs_k(const __nv_bfloat16* __restrict__ Ah, const __nv_bfloat16* __restrict__ Al,
                          const __nv_bfloat16* __restrict__ Wh, const __nv_bfloat16* __restrict__ Wl,
                          const float* __restrict__ bias, const float* __restrict__ Rm,
                          float* __restrict__ Cf, __nv_bfloat16* __restrict__ Ch,
                          __nv_bfloat16* __restrict__ Cl, int M, int N, int K) {
    __shared__ __nv_bfloat16 As[2][2][64][40];   // [stage][hi/lo][row][col]
    __shared__ __nv_bfloat16 Ws[2][2][64][40];
    int tid = threadIdx.x, lane = tid & 31, wid = tid >> 5;
    int bm = blockIdx.y << 6, bn = blockIdx.x << 6;
    int wm = (wid >> 1) << 4, wn = (wid & 1) << 5;

    float acc[4][4];
#pragma unroll
    for (int j = 0; j < 4; j++)
#pragma unroll
        for (int k = 0; k < 4; k++) acc[j][k] = 0.f;

    int lr = tid >> 2;             // row 0..63
    int lc = (tid & 3) << 3;       // col chunk 0,8,16,24
    const __nv_bfloat16* gAh = Ah + (size_t)(bm + lr) * K + lc;
    const __nv_bfloat16* gAl = Al + (size_t)(bm + lr) * K + lc;
    const __nv_bfloat16* gWh = Wh + (size_t)(bn + lr) * K + lc;
    const __nv_bfloat16* gWl = Wl + (size_t)(bn + lr) * K + lc;

    int a_r = lane & 15, a_c = (lane >> 4) << 3;
    int b_r = (lane & 7) + ((lane >> 4) << 3), b_c = ((lane >> 3) & 1) << 3;
    int KT = K >> 5;

    // preload stage 0
    {
        cpa16(&As[0][0][lr][lc], gAh);
        cpa16(&As[0][1][lr][lc], gAl);
        cpa16(&Ws[0][0][lr][lc], gWh);
        cpa16(&Ws[0][1][lr][lc], gWl);
        cpacommit();
    }

    for (int kt = 0; kt < KT; kt++) {
        int cur = kt & 1;
        if (kt + 1 < KT) {
            int k0 = (kt + 1) << 5;
            int nx = cur ^ 1;
            cpa16(&As[nx][0][lr][lc], gAh + k0);
            cpa16(&As[nx][1][lr][lc], gAl + k0);
            cpa16(&Ws[nx][0][lr][lc], gWh + k0);
            cpa16(&Ws[nx][1][lr][lc], gWl + k0);
            cpacommit();
            cpawait<1>();
        } else {
            cpawait<0>();
        }
        __syncthreads();
#pragma unroll
        for (int ks = 0; ks < 2; ks++) {
            uint32_t ah[4], al[4], bh[4][2], bl[4][2];
            ldm4(ah, &As[cur][0][wm + a_r][(ks << 4) + a_c]);
            ldm4(al, &As[cur][1][wm + a_r][(ks << 4) + a_c]);
#pragma unroll
            for (int np = 0; np < 2; np++) {
                uint32_t t4[4];
                ldm4(t4, &Ws[cur][0][wn + (np << 4) + b_r][(ks << 4) + b_c]);
                bh[np * 2][0] = t4[0]; bh[np * 2][1] = t4[1];
                bh[np * 2 + 1][0] = t4[2]; bh[np * 2 + 1][1] = t4[3];
                ldm4(t4, &Ws[cur][1][wn + (np << 4) + b_r][(ks << 4) + b_c]);
                bl[np * 2][0] = t4[0]; bl[np * 2][1] = t4[1];
                bl[np * 2 + 1][0] = t4[2]; bl[np * 2 + 1][1] = t4[3];
            }
#pragma unroll
            for (int nt = 0; nt < 4; nt++) {
                mma_bf16(acc[nt], ah, bh[nt]);
                mma_bf16(acc[nt], ah, bl[nt]);
                mma_bf16(acc[nt], al, bh[nt]);
            }
        }
        __syncthreads();
    }

    int g = lane >> 2, qd = lane & 3;
    int r0 = bm + wm + g;
#pragma unroll
    for (int nt = 0; nt < 4; nt++) {
        int col = bn + wn + (nt << 3) + (qd << 1);
        float b0 = bias[col], b1 = bias[col + 1];
        float v0 = acc[nt][0] + b0, v1 = acc[nt][1] + b1;
        float v2 = acc[nt][2] + b0, v3 = acc[nt][3] + b1;
        if (RESID) {
            v0 += Rm[(size_t)r0 * N + col];       v1 += Rm[(size_t)r0 * N + col + 1];
            v2 += Rm[(size_t)(r0 + 8) * N + col]; v3 += Rm[(size_t)(r0 + 8) * N + col + 1];
        }
        if (RELU) {
            v0 = fmaxf(v0, 0.f); v1 = fmaxf(v1, 0.f);
            v2 = fmaxf(v2, 0.f); v3 = fmaxf(v3, 0.f);
        }
        size_t i0 = (size_t)r0 * N + col, i1 = (size_t)(r0 + 8) * N + col;
        if (OMODE == OUT_F32) {
            *(float2*)&Cf[i0] = make_float2(v0, v1);
            *(float2*)&Cf[i1] = make_float2(v2, v3);
        } else if (OMODE == OUT_BF16) {
            *(uint32_t*)&Ch[i0] = packbf(v0, v1);
            *(uint32_t*)&Ch[i1] = packbf(v2, v3);
        } else if (OMODE == OUT_SPLIT) {
            uint32_t ph, pl;
            split2(v0, v1, ph, pl);
            *(uint32_t*)&Ch[i0] = ph; *(uint32_t*)&Cl[i0] = pl;
            split2(v2, v3, ph, pl);
            *(uint32_t*)&Ch[i1] = ph; *(uint32_t*)&Cl[i1] = pl;
        } else {  // OUT_KV
            __nv_bfloat16* dst = (col < CM) ? Ch : Cl;
            int cc = col & (CM - 1);
            *(uint32_t*)&dst[(size_t)r0 * CM + cc] = packbf(v0, v1);
            *(uint32_t*)&dst[(size_t)(r0 + 8) * CM + cc] = packbf(v2, v3);
        }
    }
}

// ---------------- flash attention, cp.async double-buffered kv tiles ----------------
__global__ void attn_mma_k(const __nv_bfloat16* __restrict__ Qb, const __nv_bfloat16* __restrict__ Kb,
                           const __nv_bfloat16* __restrict__ Vb,
                           __nv_bfloat16* __restrict__ Oh, __nv_bfloat16* __restrict__ Ol) {
    __shared__ __nv_bfloat16 Qs[64][40];
    __shared__ __nv_bfloat16 Ks[2][64][40];
    __shared__ __nv_bfloat16 Vs[2][64][40];
    int tid = threadIdx.x, lane = tid & 31, wid = tid >> 5;
    int h = blockIdx.y, q0 = blockIdx.x << 6;
    int hc = h << 5;

    int ldr = tid >> 1, ldc = (tid & 1) << 4;   // row 0..63, col 0/16

    // preload kv tile 0 (async) before Q staging
    {
        const __nv_bfloat16* pk = Kb + (size_t)ldr * CM + hc + ldc;
        const __nv_bfloat16* pv = Vb + (size_t)ldr * CM + hc + ldc;
        cpa16(&Ks[0][ldr][ldc], pk);
        cpa16(&Ks[0][ldr][ldc + 8], pk + 8);
        cpa16(&Vs[0][ldr][ldc], pv);
        cpa16(&Vs[0][ldr][ldc + 8], pv + 8);
        cpacommit();
    }
    {
        const uint4* p = (const uint4*)(Qb + (size_t)(q0 + ldr) * CM + hc + ldc);
        *(uint4*)&Qs[ldr][ldc] = p[0];
        *(uint4*)&Qs[ldr][ldc + 8] = p[1];
    }
    __syncthreads();

    int a_r = lane & 15, a_c = (lane >> 4) << 3;
    uint32_t qf[2][4];
    ldm4(qf[0], &Qs[(wid << 4) + a_r][a_c]);
    ldm4(qf[1], &Qs[(wid << 4) + a_r][16 + a_c]);

    float o[4][4];
#pragma unroll
    for (int i = 0; i < 4; i++)
#pragma unroll
        for (int j = 0; j < 4; j++) o[i][j] = 0.f;
    float m0 = -1e30f, m1 = -1e30f, l0 = 0.f, l1 = 0.f;

    int b_r = (lane & 7) + ((lane >> 4) << 3), b_c = ((lane >> 3) & 1) << 3;
    int NT = LK / 64;

    for (int t = 0; t < NT; t++) {
        int cur = t & 1;
        if (t + 1 < NT) {
            int nx = cur ^ 1;
            const __nv_bfloat16* pk = Kb + (size_t)((t + 1) * 64 + ldr) * CM + hc + ldc;
            const __nv_bfloat16* pv = Vb + (size_t)((t + 1) * 64 + ldr) * CM + hc + ldc;
            cpa16(&Ks[nx][ldr][ldc], pk);
            cpa16(&Ks[nx][ldr][ldc + 8], pk + 8);
            cpa16(&Vs[nx][ldr][ldc], pv);
            cpa16(&Vs[nx][ldr][ldc + 8], pv + 8);
            cpacommit();
            cpawait<1>();
        } else {
            cpawait<0>();
        }
        __syncthreads();

        float s[8][4];
#pragma unroll
        for (int j = 0; j < 8; j++)
#pragma unroll
            for (int c = 0; c < 4; c++) s[j][c] = 0.f;
#pragma unroll
        for (int ks = 0; ks < 2; ks++) {
#pragma unroll
            for (int jp = 0; jp < 4; jp++) {
                uint32_t t4[4];
                ldm4(t4, &Ks[cur][(jp << 4) + b_r][(ks << 4) + b_c]);
                uint32_t bb0[2] = {t4[0], t4[1]};
                uint32_t bb1[2] = {t4[2], t4[3]};
                mma_bf16(s[jp * 2], qf[ks], bb0);
                mma_bf16(s[jp * 2 + 1], qf[ks], bb1);
            }
        }
#pragma unroll
        for (int j = 0; j < 8; j++) {
            s[j][0] *= SCALE; s[j][1] *= SCALE; s[j][2] *= SCALE; s[j][3] *= SCALE;
        }

        float rmax0 = -1e30f, rmax1 = -1e30f;
#pragma unroll
        for (int j = 0; j < 8; j++) {
            rmax0 = fmaxf(rmax0, fmaxf(s[j][0], s[j][1]));
            rmax1 = fmaxf(rmax1, fmaxf(s[j][2], s[j][3]));
        }
        rmax0 = fmaxf(rmax0, __shfl_xor_sync(0xffffffffu, rmax0, 1));
        rmax0 = fmaxf(rmax0, __shfl_xor_sync(0xffffffffu, rmax0, 2));
        rmax1 = fmaxf(rmax1, __shfl_xor_sync(0xffffffffu, rmax1, 1));
        rmax1 = fmaxf(rmax1, __shfl_xor_sync(0xffffffffu, rmax1, 2));

        float mn0 = fmaxf(m0, rmax0), mn1 = fmaxf(m1, rmax1);
        float c0 = __expf(m0 - mn0), c1 = __expf(m1 - mn1);
        float sum0 = 0.f, sum1 = 0.f;
        uint32_t pa[4][4];
#pragma unroll
        for (int jj = 0; jj < 4; jj++) {
            float p00 = __expf(s[2 * jj][0] - mn0),     p01 = __expf(s[2 * jj][1] - mn0);
            float p02 = __expf(s[2 * jj][2] - mn1),     p03 = __expf(s[2 * jj][3] - mn1);
            float p10 = __expf(s[2 * jj + 1][0] - mn0), p11 = __expf(s[2 * jj + 1][1] - mn0);
            float p12 = __expf(s[2 * jj + 1][2] - mn1), p13 = __expf(s[2 * jj + 1][3] - mn1);
            sum0 += p00 + p01 + p10 + p11;
            sum1 += p02 + p03 + p12 + p13;
            pa[jj][0] = packbf(p00, p01);
            pa[jj][1] = packbf(p02, p03);
            pa[jj][2] = packbf(p10, p11);
            pa[jj][3] = packbf(p12, p13);
        }
        sum0 += __shfl_xor_sync(0xffffffffu, sum0, 1);
        sum0 += __shfl_xor_sync(0xffffffffu, sum0, 2);
        sum1 += __shfl_xor_sync(0xffffffffu, sum1, 1);
        sum1 += __shfl_xor_sync(0xffffffffu, sum1, 2);
        l0 = l0 * c0 + sum0;
        l1 = l1 * c1 + sum1;
        m0 = mn0; m1 = mn1;
#pragma unroll
        for (int nt = 0; nt < 4; nt++) {
            o[nt][0] *= c0; o[nt][1] *= c0; o[nt][2] *= c1; o[nt][3] *= c1;
        }

#pragma unroll
        for (int jj = 0; jj < 4; jj++) {
            uint32_t t4[4];
            ldm4t(t4, &Vs[cur][(jj << 4) + (lane & 15)][(lane >> 4) << 3]);
            {
                uint32_t bb0[2] = {t4[0], t4[1]};
                uint32_t bb1[2] = {t4[2], t4[3]};
                mma_bf16(o[0], pa[jj], bb0);
                mma_bf16(o[1], pa[jj], bb1);
            }
            ldm4t(t4, &Vs[cur][(jj << 4) + (lane & 15)][16 + ((lane >> 4) << 3)]);
            {
                uint32_t bb0[2] = {t4[0], t4[1]};
                uint32_t bb1[2] = {t4[2], t4[3]};
                mma_bf16(o[2], pa[jj], bb0);
                mma_bf16(o[3], pa[jj], bb1);
            }
        }
        __syncthreads();
    }

    float inv0 = 1.f / l0, inv1 = 1.f / l1;
    int g = lane >> 2, qd = lane & 3;
    int row0 = q0 + (wid << 4) + g;
#pragma unroll
    for (int nt = 0; nt < 4; nt++) {
        int col = hc + (nt << 3) + (qd << 1);
        uint32_t ph, pl;
        split2(o[nt][0] * inv0, o[nt][1] * inv0, ph, pl);
        *(uint32_t*)&Oh[(size_t)row0 * CM + col] = ph;
        *(uint32_t*)&Ol[(size_t)row0 * CM + col] = pl;
        split2(o[nt][2] * inv1, o[nt][3] * inv1, ph, pl);
        *(uint32_t*)&Oh[(size_t)(row0 + 8) * CM + col] = ph;
        *(uint32_t*)&Ol[(size_t)(row0 + 8) * CM + col] = pl;
    }
}

// ---------------- LayerNorm ----------------
template <bool SPLIT>
__global__ void ln_k(const float* __restrict__ X, const float* __restrict__ g,
                     const float* __restrict__ b, float* __restrict__ Y,
                     __nv_bfloat16* __restrict__ Yh, __nv_bfloat16* __restrict__ Yl) {
    int row = blockIdx.x;
    int c = threadIdx.x;
    float v = X[row * CM + c];
    float s = v, s2 = v * v;
#pragma unroll
    for (int o = 16; o > 0; o >>= 1) {
        s += __shfl_xor_sync(0xffffffffu, s, o);
        s2 += __shfl_xor_sync(0xffffffffu, s2, o);
    }
    __shared__ float rs[8], rs2[8];
    int w = c >> 5, lane = c & 31;
    if (lane == 0) { rs[w] = s; rs2[w] = s2; }
    __syncthreads();
    float tot = 0.f, tot2 = 0.f;
#pragma unroll
    for (int i = 0; i < 8; i++) { tot += rs[i]; tot2 += rs2[i]; }
    float mean = tot * (1.f / 256.f);
    float var = tot2 * (1.f / 256.f) - mean * mean;
    float is = rsqrtf(var + 1e-5f);
    float y = (v - mean) * is * g[c] + b[c];
    Y[row * CM + c] = y;
    if (SPLIT) {
        __nv_bfloat16 hh = __float2bfloat16_rn(y);
        Yh[row * CM + c] = hh;
        Yl[row * CM + c] = __float2bfloat16_rn(y - __bfloat162float(hh));
    }
}

// ---------------- launcher ----------------
#define SYM(p, s) cudaGetSymbolAddress((void**)&p, s)

extern "C" void kernel_launch(void* const* d_in, const int* in_sizes, int n_in,
                              void* d_out, int out_size) {
    const float* x_ego  = (const float*)d_in[0];
    const float* x_agent = (const float*)d_in[1];
    const float* Wf1 = (const float*)d_in[2];
    const float* bf1 = (const float*)d_in[3];
    const float* Wf2 = (const float*)d_in[4];
    const float* bf2 = (const float*)d_in[5];
    const float* Wf3 = (const float*)d_in[6];
    const float* bf3 = (const float*)d_in[7];
    const float* Wqkv = (const float*)d_in[8];
    const float* bqkv = (const float*)d_in[9];
    const float* Wo = (const float*)d_in[10];
    const float* bo = (const float*)d_in[11];
    const float* W1 = (const float*)d_in[12];
    const float* b1 = (const float*)d_in[13];
    const float* W2 = (const float*)d_in[14];
    const float* b2 = (const float*)d_in[15];
    const float* g1 = (const float*)d_in[16];
    const float* be1 = (const float*)d_in[17];
    const float* g2 = (const float*)d_in[18];
    const float* be2 = (const float*)d_in[19];
    const int* pos_ego = (const int*)d_in[20];
    const int* pos_agent = (const int*)d_in[21];
    float* out = (float*)d_out;

    float *p_fused, *p_q, *p_res1, *p_yq, *p_res2;
    SYM(p_fused, d_fused); SYM(p_q, d_q); SYM(p_res1, d_res1);
    SYM(p_yq, d_yq); SYM(p_res2, d_res2);

    __nv_bfloat16 *fi_h, *fi_l, *h1_h, *h1_l, *h2_h, *h2_l, *q_h, *q_l, *kv_h, *kv_l;
    __nv_bfloat16 *Qb, *Kb, *Vb, *at_h, *at_l, *yq_h, *yq_l, *ff_h, *ff_l;
    __nv_bfloat16 *wf1_h, *wf1_l, *wf2_h, *wf2_l, *wf3_h, *wf3_l;
    __nv_bfloat16 *wqkv_h, *wqkv_l, *wo_h, *wo_l, *w1_h, *w1_l, *w2_h, *w2_l;
    SYM(fi_h, b_fi_h); SYM(fi_l, b_fi_l);
    SYM(h1_h, b_h1_h); SYM(h1_l, b_h1_l);
    SYM(h2_h, b_h2_h); SYM(h2_l, b_h2_l);
    SYM(q_h, b_q_h); SYM(q_l, b_q_l);
    SYM(kv_h, b_kv_h); SYM(kv_l, b_kv_l);
    SYM(Qb, b_Q); SYM(Kb, b_K); SYM(Vb, b_V);
    SYM(at_h, b_at_h); SYM(at_l, b_at_l);
    SYM(yq_h, b_yq_h); SYM(yq_l, b_yq_l);
    SYM(ff_h, b_ff_h); SYM(ff_l, b_ff_l);
    SYM(wf1_h, b_wf1_h); SYM(wf1_l, b_wf1_l);
    SYM(wf2_h, b_wf2_h); SYM(wf2_l, b_wf2_l);
    SYM(wf3_h, b_wf3_h); SYM(wf3_l, b_wf3_l);
    SYM(wqkv_h, b_wqkv_h); SYM(wqkv_l, b_wqkv_l);
    SYM(wo_h, b_wo_h); SYM(wo_l, b_wo_l);
    SYM(w1_h, b_w1_h); SYM(w1_l, b_w1_l);
    SYM(w2_h, b_w2_h); SYM(w2_l, b_w2_l);

    // streams/events for fork-join graph branches (host objects, created once)
    static cudaStream_t sA = nullptr, sB = nullptr;
    static cudaEvent_t ev0, ev1, ev2;
    if (!sA) {
        cudaStreamCreateWithFlags(&sA, cudaStreamNonBlocking);
        cudaStreamCreateWithFlags(&sB, cudaStreamNonBlocking);
        cudaEventCreateWithFlags(&ev0, cudaEventDisableTiming);
        cudaEventCreateWithFlags(&ev1, cudaEventDisableTiming);
        cudaEventCreateWithFlags(&ev2, cudaEventDisableTiming);
    }

    WS ws;
    ws.s[0] = Wf1;  ws.h[0] = wf1_h;  ws.l[0] = wf1_l;
    ws.s[1] = Wf2;  ws.h[1] = wf2_h;  ws.l[1] = wf2_l;
    ws.s[2] = Wf3;  ws.h[2] = wf3_h;  ws.l[2] = wf3_l;
    ws.s[3] = Wqkv; ws.h[3] = wqkv_h; ws.l[3] = wqkv_l;
    ws.s[4] = Wo;   ws.h[4] = wo_h;   ws.l[4] = wo_l;
    ws.s[5] = W1;   ws.h[5] = w1_h;   ws.l[5] = w1_l;
    ws.s[6] = W2;   ws.h[6] = w2_h;   ws.l[6] = w2_l;
    ws.off[0] = 0;       ws.off[1] = 131072;  ws.off[2] = 196608; ws.off[3] = 262144;
    ws.off[4] = 458752;  ws.off[5] = 524288;  ws.off[6] = 786432; ws.off[7] = 1048576;

    // fork point
    cudaEventRecord(ev0, 0);

    // branch A: weight splits
    cudaStreamWaitEvent(sA, ev0, 0);
    wsplit_k<<<4096, 256, 0, sA>>>(ws);
    cudaEventRecord(ev1, sA);

    // branch B: kv build + K/V projection (needs weights)
    cudaStreamWaitEvent(sB, ev0, 0);
    build_kv_k<<<(LK * CM) / 256, 256, 0, sB>>>(x_ego, x_agent);
    cudaStreamWaitEvent(sB, ev1, 0);
    gemm_bs_k<OUT_KV, false, false><<<dim3(2 * CM / 64, LK / 64), 256, 0, sB>>>(
        kv_h, kv_l, wqkv_h + CM * CM, wqkv_l + CM * CM, bqkv + CM, nullptr,
        nullptr, Kb, Vb, LK, 2 * CM, CM);
    cudaEventRecord(ev2, sB);

    // main branch: hash matching, fusion MLP, Q path
    ht_init_k<<<HT_SIZE / 256, 256>>>();
    ht_insert_k<<<LA / 256, 256>>>(pos_agent);
    ht_lookup_k<<<LE / 256, 256>>>(pos_ego);
    compact_scan_k<<<1, 1024>>>();
    build_fusedin_k<<<(LE * 2 * CM) / 256, 256>>>(x_ego, x_agent);
    cudaStreamWaitEvent(0, ev1, 0);
    gemm_bs_k<OUT_SPLIT, true, false><<<dim3(CM / 64, LE / 64), 256>>>(
        fi_h, fi_l, wf1_h, wf1_l, bf1, nullptr, nullptr, h1_h, h1_l, LE, CM, 2 * CM);
    gemm_bs_k<OUT_SPLIT, true, false><<<dim3(CM / 64, LE / 64), 256>>>(
        h1_h, h1_l, wf2_h, wf2_l, bf2, nullptr, nullptr, h2_h, h2_l, LE, CM, CM);
    gemm_bs_k<OUT_F32, false, false><<<dim3(CM / 64, LE / 64), 256>>>(
        h2_h, h2_l, wf3_h, wf3_l, bf3, nullptr, p_fused, nullptr, nullptr, LE, CM, CM);
    build_q_k<<<(LQ * CM) / 256, 256>>>(x_ego, x_agent);
    gemm_bs_k<OUT_BF16, false, false><<<dim3(CM / 64, LQ / 64), 256>>>(
        q_h, q_l, wqkv_h, wqkv_l, bqkv, nullptr, nullptr, Qb, nullptr, LQ, CM, CM);

    // join: attention needs K/V from branch B
    cudaStreamWaitEvent(0, ev2, 0);
    attn_mma_k<<<dim3(LQ / 64, HN), 128>>>(Qb, Kb, Vb, at_h, at_l);

    gemm_bs_k<OUT_F32, false, true><<<dim3(CM / 64, LQ / 64), 256>>>(
        at_h, at_l, wo_h, wo_l, bo, p_q, p_res1, nullptr, nullptr, LQ, CM, CM);
    ln_k<true><<<LQ, 256>>>(p_res1, g1, be1, p_yq, yq_h, yq_l);
    gemm_bs_k<OUT_SPLIT, true, false><<<dim3(DF / 64, LQ / 64), 256>>>(
        yq_h, yq_l, w1_h, w1_l, b1, nullptr, nullptr, ff_h, ff_l, LQ, DF, CM);
    gemm_bs_k<OUT_F32, false, true><<<dim3(CM / 64, LQ / 64), 256>>>(
        ff_h, ff_l, w2_h, w2_l, b2, p_yq, p_res2, nullptr, nullptr, LQ, CM, DF);
    ln_k<false><<<LQ, 256>>>(p_res2, g2, be2, out, nullptr, nullptr);
}